// round 1
// baseline (speedup 1.0000x reference)
#include <cuda_runtime.h>
#include <math.h>

#define SEQ 8192
#define DM  2048

#define BM 128
#define BN 128
#define BK 16
#define TM 8
#define TN 8
#define NTHREADS 256   // (BM/TM)*(BN/TN)

// ---- scratch (allocation-free: device globals) ----
__device__ float g_Q[(size_t)SEQ * DM];
__device__ float g_K[(size_t)SEQ * DM];
__device__ float g_V[(size_t)SEQ * DM];
__device__ float g_S[(size_t)SEQ * SEQ];

// =====================================================================
// C[M,N] = A[M,K] @ B[N,K]^T   (both operands K-contiguous, row-major)
// Used for: Q/K/V = X @ W^T  and  S = Q @ K^T
// =====================================================================
__global__ __launch_bounds__(NTHREADS)
void gemm_nt(const float* __restrict__ A, const float* __restrict__ B,
             float* __restrict__ C, int M, int N, int K)
{
    __shared__ float As[BK][BM];
    __shared__ float Bs[BK][BN];

    const int tid = threadIdx.x;
    const int tx  = tid % (BN / TN);   // 0..15
    const int ty  = tid / (BN / TN);   // 0..15

    const long row0 = (long)blockIdx.y * BM;
    const long col0 = (long)blockIdx.x * BN;

    // loader coords: 256 threads, each loads one float4 per 64-row group
    const int lr = tid >> 2;          // 0..63
    const int lk = (tid & 3) * 4;     // 0,4,8,12

    float acc[TM][TN];
#pragma unroll
    for (int i = 0; i < TM; i++)
#pragma unroll
        for (int j = 0; j < TN; j++) acc[i][j] = 0.0f;

    for (int k0 = 0; k0 < K; k0 += BK) {
#pragma unroll
        for (int r = 0; r < BM; r += 64) {
            float4 v = *(const float4*)(A + (row0 + lr + r) * (long)K + k0 + lk);
            As[lk + 0][lr + r] = v.x;
            As[lk + 1][lr + r] = v.y;
            As[lk + 2][lr + r] = v.z;
            As[lk + 3][lr + r] = v.w;
        }
#pragma unroll
        for (int r = 0; r < BN; r += 64) {
            float4 v = *(const float4*)(B + (col0 + lr + r) * (long)K + k0 + lk);
            Bs[lk + 0][lr + r] = v.x;
            Bs[lk + 1][lr + r] = v.y;
            Bs[lk + 2][lr + r] = v.z;
            Bs[lk + 3][lr + r] = v.w;
        }
        __syncthreads();

#pragma unroll
        for (int kk = 0; kk < BK; kk++) {
            float a[TM], b[TN];
            *(float4*)&a[0] = *(const float4*)&As[kk][ty * TM];
            *(float4*)&a[4] = *(const float4*)&As[kk][ty * TM + 4];
            *(float4*)&b[0] = *(const float4*)&Bs[kk][tx * TN];
            *(float4*)&b[4] = *(const float4*)&Bs[kk][tx * TN + 4];
#pragma unroll
            for (int i = 0; i < TM; i++)
#pragma unroll
                for (int j = 0; j < TN; j++)
                    acc[i][j] = fmaf(a[i], b[j], acc[i][j]);
        }
        __syncthreads();
    }

#pragma unroll
    for (int i = 0; i < TM; i++) {
        long r = row0 + ty * TM + i;
        float4* cp = (float4*)(C + r * (long)N + col0 + tx * TN);
        cp[0] = make_float4(acc[i][0], acc[i][1], acc[i][2], acc[i][3]);
        cp[1] = make_float4(acc[i][4], acc[i][5], acc[i][6], acc[i][7]);
    }
}

// =====================================================================
// C[M,N] = A[M,K] @ B[K,N]   (A K-contiguous, B N-contiguous)
// Used for: O = P @ V
// =====================================================================
__global__ __launch_bounds__(NTHREADS)
void gemm_nn(const float* __restrict__ A, const float* __restrict__ B,
             float* __restrict__ C, int M, int N, int K)
{
    __shared__ float As[BK][BM];
    __shared__ float Bs[BK][BN];

    const int tid = threadIdx.x;
    const int tx  = tid % (BN / TN);
    const int ty  = tid / (BN / TN);

    const long row0 = (long)blockIdx.y * BM;
    const long col0 = (long)blockIdx.x * BN;

    const int lr = tid >> 2;          // 0..63 (A loader)
    const int lk = (tid & 3) * 4;

    const int bk = tid >> 5;          // 0..7  (B loader)
    const int bn = (tid & 31) * 4;    // 0..124

    float acc[TM][TN];
#pragma unroll
    for (int i = 0; i < TM; i++)
#pragma unroll
        for (int j = 0; j < TN; j++) acc[i][j] = 0.0f;

    for (int k0 = 0; k0 < K; k0 += BK) {
#pragma unroll
        for (int r = 0; r < BM; r += 64) {
            float4 v = *(const float4*)(A + (row0 + lr + r) * (long)K + k0 + lk);
            As[lk + 0][lr + r] = v.x;
            As[lk + 1][lr + r] = v.y;
            As[lk + 2][lr + r] = v.z;
            As[lk + 3][lr + r] = v.w;
        }
#pragma unroll
        for (int p = 0; p < BK; p += 8) {
            float4 v = *(const float4*)(B + (long)(k0 + bk + p) * N + col0 + bn);
            *(float4*)&Bs[bk + p][bn] = v;
        }
        __syncthreads();

#pragma unroll
        for (int kk = 0; kk < BK; kk++) {
            float a[TM], b[TN];
            *(float4*)&a[0] = *(const float4*)&As[kk][ty * TM];
            *(float4*)&a[4] = *(const float4*)&As[kk][ty * TM + 4];
            *(float4*)&b[0] = *(const float4*)&Bs[kk][tx * TN];
            *(float4*)&b[4] = *(const float4*)&Bs[kk][tx * TN + 4];
#pragma unroll
            for (int i = 0; i < TM; i++)
#pragma unroll
                for (int j = 0; j < TN; j++)
                    acc[i][j] = fmaf(a[i], b[j], acc[i][j]);
        }
        __syncthreads();
    }

#pragma unroll
    for (int i = 0; i < TM; i++) {
        long r = row0 + ty * TM + i;
        float4* cp = (float4*)(C + r * (long)N + col0 + tx * TN);
        cp[0] = make_float4(acc[i][0], acc[i][1], acc[i][2], acc[i][3]);
        cp[1] = make_float4(acc[i][4], acc[i][5], acc[i][6], acc[i][7]);
    }
}

// =====================================================================
// In-place row softmax of P[SEQ,SEQ], with scaling by 1/sqrt(DM) folded
// in BEFORE the exp (softmax(s*scale)). One block per row; each thread
// keeps its 32 elements in registers: one global read + one write.
// =====================================================================
__global__ __launch_bounds__(256)
void softmax_rows(float* __restrict__ P)
{
    const long row = blockIdx.x;
    float4* rp = (float4*)(P + row * (long)SEQ);
    const int tid = threadIdx.x;

    const float scale = 0.02209708691207961f;  // 1/sqrt(2048)

    float4 v[8];
    float mx = -INFINITY;
#pragma unroll
    for (int i = 0; i < 8; i++) {
        v[i] = rp[tid + i * 256];
        mx = fmaxf(mx, fmaxf(fmaxf(v[i].x, v[i].y), fmaxf(v[i].z, v[i].w)));
    }

    __shared__ float red[256];
    red[tid] = mx;
    __syncthreads();
    for (int s = 128; s > 0; s >>= 1) {
        if (tid < s) red[tid] = fmaxf(red[tid], red[tid + s]);
        __syncthreads();
    }
    mx = red[0];
    __syncthreads();

    float sum = 0.0f;
#pragma unroll
    for (int i = 0; i < 8; i++) {
        v[i].x = __expf((v[i].x - mx) * scale);
        v[i].y = __expf((v[i].y - mx) * scale);
        v[i].z = __expf((v[i].z - mx) * scale);
        v[i].w = __expf((v[i].w - mx) * scale);
        sum += (v[i].x + v[i].y) + (v[i].z + v[i].w);
    }

    red[tid] = sum;
    __syncthreads();
    for (int s = 128; s > 0; s >>= 1) {
        if (tid < s) red[tid] += red[tid + s];
        __syncthreads();
    }
    const float inv = 1.0f / red[0];

#pragma unroll
    for (int i = 0; i < 8; i++) {
        v[i].x *= inv; v[i].y *= inv; v[i].z *= inv; v[i].w *= inv;
        rp[tid + i * 256] = v[i];
    }
}

// =====================================================================
// launch
// =====================================================================
extern "C" void kernel_launch(void* const* d_in, const int* in_sizes, int n_in,
                              void* d_out, int out_size)
{
    (void)in_sizes; (void)n_in; (void)out_size;

    const float* X  = (const float*)d_in[0];
    const float* Wq = (const float*)d_in[1];
    const float* Wk = (const float*)d_in[2];
    const float* Wv = (const float*)d_in[3];
    float* O = (float*)d_out;

    float *Q, *K, *V, *Smat;
    cudaGetSymbolAddress((void**)&Q,    g_Q);
    cudaGetSymbolAddress((void**)&K,    g_K);
    cudaGetSymbolAddress((void**)&V,    g_V);
    cudaGetSymbolAddress((void**)&Smat, g_S);

    dim3 blk(NTHREADS);

    // Q/K/V = X @ W^T   : M=SEQ, N=DM, K=DM
    dim3 g1(DM / BN, SEQ / BM);
    gemm_nt<<<g1, blk>>>(X, Wq, Q, SEQ, DM, DM);
    gemm_nt<<<g1, blk>>>(X, Wk, K, SEQ, DM, DM);
    gemm_nt<<<g1, blk>>>(X, Wv, V, SEQ, DM, DM);

    // S = Q @ K^T       : M=SEQ, N=SEQ, K=DM  (scale folded into softmax)
    dim3 g2(SEQ / BN, SEQ / BM);
    gemm_nt<<<g2, blk>>>(Q, K, Smat, SEQ, SEQ, DM);

    // P = softmax(S * 1/sqrt(DM)) row-wise, in place
    softmax_rows<<<SEQ, 256>>>(Smat);

    // O = P @ V         : M=SEQ, N=DM, K=SEQ
    dim3 g3(DM / BN, SEQ / BM);
    gemm_nn<<<g3, blk>>>(Smat, V, O, SEQ, DM, SEQ);
}

// round 4
// speedup vs baseline: 2.9068x; 2.9068x over previous
#include <cuda_runtime.h>
#include <cuda_bf16.h>
#include <cstdint>
#include <math.h>

#define SEQ 8192
#define DM  2048
typedef __nv_bfloat16 bf16;

// ======================= scratch (device globals) =======================
__device__ bf16  g_Xhi[(size_t)SEQ * DM], g_Xlo[(size_t)SEQ * DM];
__device__ bf16  g_Wqhi[(size_t)DM * DM], g_Wqlo[(size_t)DM * DM];
__device__ bf16  g_Wkhi[(size_t)DM * DM], g_Wklo[(size_t)DM * DM];
__device__ bf16  g_Wvhi[(size_t)DM * DM], g_Wvlo[(size_t)DM * DM];
__device__ bf16  g_Qhi[(size_t)SEQ * DM], g_Qlo[(size_t)SEQ * DM];
__device__ bf16  g_Khi[(size_t)SEQ * DM], g_Klo[(size_t)SEQ * DM];
__device__ bf16  g_Vhi[(size_t)SEQ * DM], g_Vlo[(size_t)SEQ * DM];
__device__ float g_S[(size_t)SEQ * SEQ];
__device__ bf16  g_Phi[(size_t)SEQ * SEQ], g_Plo[(size_t)SEQ * SEQ];

// ======================= helpers =======================
__device__ __forceinline__ uint32_t smem_u32(const void* p) {
    uint32_t a;
    asm("{ .reg .u64 t; cvta.to.shared.u64 t, %1; cvt.u32.u64 %0, t; }" : "=r"(a) : "l"(p));
    return a;
}
#define CP16(sm, gp) \
    asm volatile("cp.async.cg.shared.global [%0], [%1], 16;" :: "r"(sm), "l"(gp))
#define CP_COMMIT() asm volatile("cp.async.commit_group;")
#define CP_WAIT(n)  asm volatile("cp.async.wait_group %0;" :: "n"(n) : "memory")

__device__ __forceinline__ void ldsm_x4(uint32_t* r, uint32_t a) {
    asm volatile("ldmatrix.sync.aligned.m8n8.x4.shared.b16 {%0,%1,%2,%3}, [%4];"
        : "=r"(r[0]), "=r"(r[1]), "=r"(r[2]), "=r"(r[3]) : "r"(a));
}
__device__ __forceinline__ void ldsm_x4_t(uint32_t* r, uint32_t a) {
    asm volatile("ldmatrix.sync.aligned.m8n8.x4.trans.shared.b16 {%0,%1,%2,%3}, [%4];"
        : "=r"(r[0]), "=r"(r[1]), "=r"(r[2]), "=r"(r[3]) : "r"(a));
}
__device__ __forceinline__ void mma16816(float* c, const uint32_t* a, const uint32_t* b) {
    asm volatile("mma.sync.aligned.m16n8k16.row.col.f32.bf16.bf16.f32 "
        "{%0,%1,%2,%3}, {%4,%5,%6,%7}, {%8,%9}, {%0,%1,%2,%3};"
        : "+f"(c[0]), "+f"(c[1]), "+f"(c[2]), "+f"(c[3])
        : "r"(a[0]), "r"(a[1]), "r"(a[2]), "r"(a[3]), "r"(b[0]), "r"(b[1]));
}
__device__ __forceinline__ uint32_t pack_hi(float v0, float v1, uint32_t& lo) {
    bf16 h0 = __float2bfloat16(v0), h1 = __float2bfloat16(v1);
    bf16 l0 = __float2bfloat16(v0 - __bfloat162float(h0));
    bf16 l1 = __float2bfloat16(v1 - __bfloat162float(h1));
    lo = (uint32_t)__bfloat16_as_ushort(l0) | ((uint32_t)__bfloat16_as_ushort(l1) << 16);
    return (uint32_t)__bfloat16_as_ushort(h0) | ((uint32_t)__bfloat16_as_ushort(h1) << 16);
}

#define STAGE 65536
#define GSMEM (2 * STAGE)

// ======================= NT GEMM: C[M,N] = (Ahi+Alo)[M,K] @ (Bhi+Blo)[N,K]^T =======================
// MODE 0: write Chi/Clo bf16 row-major; MODE 2: write Cf fp32 row-major.
template <int MODE>
__global__ __launch_bounds__(512, 1)
void gemm_nt_mma(const bf16* __restrict__ Ahi, const bf16* __restrict__ Alo,
                 const bf16* __restrict__ Bhi, const bf16* __restrict__ Blo,
                 float* __restrict__ Cf, bf16* __restrict__ Chi, bf16* __restrict__ Clo,
                 int Kdim, long ldA, long ldB, long ldC)
{
    extern __shared__ char sm[];
    const uint32_t sb = smem_u32(sm);
    const int tid = threadIdx.x, wid = tid >> 5, lane = tid & 31;
    const int wm = wid >> 2, wn = wid & 3;
    const long row0 = (long)blockIdx.y * 128, col0 = (long)blockIdx.x * 128;
    const int NC = Kdim / 64;

    // loader: 1024 slots per matrix (128 rows x 8 x 16B chunks); 2 slots/thread
    uint32_t soff[2]; long aoff[2], boff[2];
#pragma unroll
    for (int j = 0; j < 2; j++) {
        int slot = tid + j * 512;
        int r = slot >> 3, c = slot & 7;
        soff[j] = (uint32_t)(r * 128 + ((c ^ (r & 7)) << 4));
        aoff[j] = (row0 + r) * ldA + c * 8;
        boff[j] = (col0 + r) * ldB + c * 8;
    }

    // ldmatrix lane addressing
    const int g = lane >> 3, lr = lane & 7;
    const int arow_b = wm * 32 + (g & 1) * 8 + lr;   // + mf*16
    const int brow_b = wn * 32 + (g & 1) * 8 + lr;   // + np*16
    const int ch_hi = g >> 1;                        // + kstep*2

    float acc[2][4][4];
#pragma unroll
    for (int i = 0; i < 2; i++)
#pragma unroll
        for (int j = 0; j < 4; j++)
#pragma unroll
            for (int q = 0; q < 4; q++) acc[i][j][q] = 0.0f;

#define NT_LOAD(buf, kb) do {                                                  \
    uint32_t s_ = sb + (uint32_t)(buf) * STAGE;                                \
    _Pragma("unroll")                                                          \
    for (int j = 0; j < 2; j++) {                                              \
        CP16(s_ +         soff[j], Ahi + aoff[j] + (kb));                      \
        CP16(s_ + 16384 + soff[j], Alo + aoff[j] + (kb));                      \
        CP16(s_ + 32768 + soff[j], Bhi + boff[j] + (kb));                      \
        CP16(s_ + 49152 + soff[j], Blo + boff[j] + (kb));                      \
    }                                                                          \
    CP_COMMIT();                                                               \
} while (0)

    NT_LOAD(0, 0);

    for (int i = 0; i < NC; i++) {
        if (i + 1 < NC) { NT_LOAD((i + 1) & 1, (long)(i + 1) * 64); CP_WAIT(1); }
        else            { CP_WAIT(0); }
        __syncthreads();
        const uint32_t As = sb + (uint32_t)(i & 1) * STAGE;
        const uint32_t Bs = As + 32768;

#pragma unroll
        for (int ks = 0; ks < 4; ks++) {
            uint32_t a[2][2][4], b[2][4][2];
#pragma unroll
            for (int comp = 0; comp < 2; comp++) {
#pragma unroll
                for (int mf = 0; mf < 2; mf++) {
                    int row = arow_b + mf * 16;
                    int ch = ks * 2 + ch_hi;
                    ldsm_x4(a[comp][mf], As + comp * 16384u + row * 128 + ((ch ^ (row & 7)) << 4));
                }
#pragma unroll
                for (int np = 0; np < 2; np++) {
                    int row = brow_b + np * 16;
                    int ch = ks * 2 + ch_hi;
                    uint32_t q[4];
                    ldsm_x4(q, Bs + comp * 16384u + row * 128 + ((ch ^ (row & 7)) << 4));
                    b[comp][np * 2][0]     = q[0]; b[comp][np * 2][1]     = q[2];
                    b[comp][np * 2 + 1][0] = q[1]; b[comp][np * 2 + 1][1] = q[3];
                }
            }
#pragma unroll
            for (int mf = 0; mf < 2; mf++)
#pragma unroll
                for (int nf = 0; nf < 4; nf++) {
                    mma16816(acc[mf][nf], a[0][mf], b[0][nf]);  // hi*hi
                    mma16816(acc[mf][nf], a[0][mf], b[1][nf]);  // hi*lo
                    mma16816(acc[mf][nf], a[1][mf], b[0][nf]);  // lo*hi
                }
        }
        __syncthreads();
    }

    // epilogue
#pragma unroll
    for (int mf = 0; mf < 2; mf++)
#pragma unroll
        for (int nf = 0; nf < 4; nf++) {
            long row = row0 + wm * 32 + mf * 16 + (lane >> 2);
            long col = col0 + wn * 32 + nf * 8 + (lane & 3) * 2;
            if (MODE == 2) {
                *(float2*)(Cf + row * ldC + col)       = make_float2(acc[mf][nf][0], acc[mf][nf][1]);
                *(float2*)(Cf + (row + 8) * ldC + col) = make_float2(acc[mf][nf][2], acc[mf][nf][3]);
            } else {
                uint32_t lo0, lo1;
                uint32_t hi0 = pack_hi(acc[mf][nf][0], acc[mf][nf][1], lo0);
                uint32_t hi1 = pack_hi(acc[mf][nf][2], acc[mf][nf][3], lo1);
                *(uint32_t*)(Chi + row * ldC + col)       = hi0;
                *(uint32_t*)(Clo + row * ldC + col)       = lo0;
                *(uint32_t*)(Chi + (row + 8) * ldC + col) = hi1;
                *(uint32_t*)(Clo + (row + 8) * ldC + col) = lo1;
            }
        }
#undef NT_LOAD
}

// ======================= NN GEMM: C[M,N] = (Ahi+Alo)[M,K] @ (Bhi+Blo)[K,N] =======================
// fp32 output. A k-contiguous (128B row-chunks), B n-contiguous (256B row-chunks).
__global__ __launch_bounds__(512, 1)
void gemm_nn_mma(const bf16* __restrict__ Ahi, const bf16* __restrict__ Alo,
                 const bf16* __restrict__ Bhi, const bf16* __restrict__ Blo,
                 float* __restrict__ Cf, int Kdim, long ldA, long ldB, long ldC)
{
    extern __shared__ char sm[];
    const uint32_t sb = smem_u32(sm);
    const int tid = threadIdx.x, wid = tid >> 5, lane = tid & 31;
    const int wm = wid >> 2, wn = wid & 3;
    const long row0 = (long)blockIdx.y * 128, col0 = (long)blockIdx.x * 128;
    const int NC = Kdim / 64;

    // A loader: 1024 slots (128 rows x 8 chunks); B loader: 1024 slots (64 k-rows x 16 chunks)
    uint32_t soffA[2], soffB[2]; long aoff[2], boff[2];
#pragma unroll
    for (int j = 0; j < 2; j++) {
        int slot = tid + j * 512;
        int ra = slot >> 3, ca = slot & 7;
        soffA[j] = (uint32_t)(ra * 128 + ((ca ^ (ra & 7)) << 4));
        aoff[j]  = (row0 + ra) * ldA + ca * 8;
        int rb = slot >> 4, cb = slot & 15;
        soffB[j] = (uint32_t)(rb * 256 + ((cb ^ (rb & 7)) << 4));
        boff[j]  = (long)rb * ldB + col0 + cb * 8;
    }

    const int g = lane >> 3, lr = lane & 7;
    const int arow_b = wm * 32 + (g & 1) * 8 + lr;       // + mf*16
    const int krow_b = (g & 1) * 8 + lr;                 // + ks*16
    const int bch_b  = wn * 4 + (g >> 1);                // + np*2

    float acc[2][4][4];
#pragma unroll
    for (int i = 0; i < 2; i++)
#pragma unroll
        for (int j = 0; j < 4; j++)
#pragma unroll
            for (int q = 0; q < 4; q++) acc[i][j][q] = 0.0f;

#define NN_LOAD(buf, kb) do {                                                  \
    uint32_t s_ = sb + (uint32_t)(buf) * STAGE;                                \
    long kb_ = (kb);                                                           \
    _Pragma("unroll")                                                          \
    for (int j = 0; j < 2; j++) {                                              \
        CP16(s_ +         soffA[j], Ahi + aoff[j] + kb_);                      \
        CP16(s_ + 16384 + soffA[j], Alo + aoff[j] + kb_);                      \
        CP16(s_ + 32768 + soffB[j], Bhi + boff[j] + kb_ * ldB);                \
        CP16(s_ + 49152 + soffB[j], Blo + boff[j] + kb_ * ldB);                \
    }                                                                          \
    CP_COMMIT();                                                               \
} while (0)

    NN_LOAD(0, 0);

    for (int i = 0; i < NC; i++) {
        if (i + 1 < NC) { NN_LOAD((i + 1) & 1, (long)(i + 1) * 64); CP_WAIT(1); }
        else            { CP_WAIT(0); }
        __syncthreads();
        const uint32_t As = sb + (uint32_t)(i & 1) * STAGE;
        const uint32_t Bs = As + 32768;

#pragma unroll
        for (int ks = 0; ks < 4; ks++) {
            uint32_t a[2][2][4], b[2][4][2];
#pragma unroll
            for (int comp = 0; comp < 2; comp++) {
#pragma unroll
                for (int mf = 0; mf < 2; mf++) {
                    int row = arow_b + mf * 16;
                    int ch = ks * 2 + (g >> 1);
                    ldsm_x4(a[comp][mf], As + comp * 16384u + row * 128 + ((ch ^ (row & 7)) << 4));
                }
#pragma unroll
                for (int np = 0; np < 2; np++) {
                    int krow = krow_b + ks * 16;
                    int ch = bch_b + np * 2;
                    uint32_t q[4];
                    ldsm_x4_t(q, Bs + comp * 16384u + krow * 256 + ((ch ^ (krow & 7)) << 4));
                    b[comp][np * 2][0]     = q[0]; b[comp][np * 2][1]     = q[1];
                    b[comp][np * 2 + 1][0] = q[2]; b[comp][np * 2 + 1][1] = q[3];
                }
            }
#pragma unroll
            for (int mf = 0; mf < 2; mf++)
#pragma unroll
                for (int nf = 0; nf < 4; nf++) {
                    mma16816(acc[mf][nf], a[0][mf], b[0][nf]);
                    mma16816(acc[mf][nf], a[0][mf], b[1][nf]);
                    mma16816(acc[mf][nf], a[1][mf], b[0][nf]);
                }
        }
        __syncthreads();
    }

#pragma unroll
    for (int mf = 0; mf < 2; mf++)
#pragma unroll
        for (int nf = 0; nf < 4; nf++) {
            long row = row0 + wm * 32 + mf * 16 + (lane >> 2);
            long col = col0 + wn * 32 + nf * 8 + (lane & 3) * 2;
            *(float2*)(Cf + row * ldC + col)       = make_float2(acc[mf][nf][0], acc[mf][nf][1]);
            *(float2*)(Cf + (row + 8) * ldC + col) = make_float2(acc[mf][nf][2], acc[mf][nf][3]);
        }
#undef NN_LOAD
}

// ======================= fp32 -> bf16 hi/lo conversion =======================
__global__ __launch_bounds__(256)
void cvt_pair(const float* __restrict__ s, bf16* __restrict__ hi, bf16* __restrict__ lo, long n4)
{
    for (long i = blockIdx.x * 256 + threadIdx.x; i < n4; i += (long)gridDim.x * 256) {
        float4 v = ((const float4*)s)[i];
        uint32_t l0, l1;
        uint32_t h0 = pack_hi(v.x, v.y, l0);
        uint32_t h1 = pack_hi(v.z, v.w, l1);
        ((uint2*)hi)[i] = make_uint2(h0, h1);
        ((uint2*)lo)[i] = make_uint2(l0, l1);
    }
}

// ======================= row softmax S -> P (bf16 hi/lo) =======================
__global__ __launch_bounds__(256)
void softmax_bf16(const float* __restrict__ S, bf16* __restrict__ Phi, bf16* __restrict__ Plo)
{
    const long row = blockIdx.x;
    const float4* rp = (const float4*)(S + row * (long)SEQ);
    const int tid = threadIdx.x;
    const float scale = 0.02209708691207961f;  // 1/sqrt(2048)

    float4 v[8];
    float mx = -INFINITY;
#pragma unroll
    for (int i = 0; i < 8; i++) {
        v[i] = rp[tid + i * 256];
        mx = fmaxf(mx, fmaxf(fmaxf(v[i].x, v[i].y), fmaxf(v[i].z, v[i].w)));
    }

    __shared__ float red[256];
    red[tid] = mx;
    __syncthreads();
    for (int s = 128; s > 0; s >>= 1) {
        if (tid < s) red[tid] = fmaxf(red[tid], red[tid + s]);
        __syncthreads();
    }
    mx = red[0];
    __syncthreads();

    float sum = 0.0f;
#pragma unroll
    for (int i = 0; i < 8; i++) {
        v[i].x = __expf((v[i].x - mx) * scale);
        v[i].y = __expf((v[i].y - mx) * scale);
        v[i].z = __expf((v[i].z - mx) * scale);
        v[i].w = __expf((v[i].w - mx) * scale);
        sum += (v[i].x + v[i].y) + (v[i].z + v[i].w);
    }
    red[tid] = sum;
    __syncthreads();
    for (int s = 128; s > 0; s >>= 1) {
        if (tid < s) red[tid] += red[tid + s];
        __syncthreads();
    }
    const float inv = 1.0f / red[0];

#pragma unroll
    for (int i = 0; i < 8; i++) {
        uint32_t l0, l1;
        uint32_t h0 = pack_hi(v[i].x * inv, v[i].y * inv, l0);
        uint32_t h1 = pack_hi(v[i].z * inv, v[i].w * inv, l1);
        long idx = row * (long)SEQ + (long)(tid + i * 256) * 4;
        ((uint2*)(Phi + idx))[0] = make_uint2(h0, h1);
        ((uint2*)(Plo + idx))[0] = make_uint2(l0, l1);
    }
}

// ======================= launch =======================
extern "C" void kernel_launch(void* const* d_in, const int* in_sizes, int n_in,
                              void* d_out, int out_size)
{
    (void)in_sizes; (void)n_in; (void)out_size;
    const float* X  = (const float*)d_in[0];
    const float* Wq = (const float*)d_in[1];
    const float* Wk = (const float*)d_in[2];
    const float* Wv = (const float*)d_in[3];
    float* O = (float*)d_out;

    bf16 *Xhi, *Xlo, *Wqhi, *Wqlo, *Wkhi, *Wklo, *Wvhi, *Wvlo;
    bf16 *Qhi, *Qlo, *Khi, *Klo, *Vhi, *Vlo, *Phi, *Plo;
    float* Smat;
    cudaGetSymbolAddress((void**)&Xhi, g_Xhi);   cudaGetSymbolAddress((void**)&Xlo, g_Xlo);
    cudaGetSymbolAddress((void**)&Wqhi, g_Wqhi); cudaGetSymbolAddress((void**)&Wqlo, g_Wqlo);
    cudaGetSymbolAddress((void**)&Wkhi, g_Wkhi); cudaGetSymbolAddress((void**)&Wklo, g_Wklo);
    cudaGetSymbolAddress((void**)&Wvhi, g_Wvhi); cudaGetSymbolAddress((void**)&Wvlo, g_Wvlo);
    cudaGetSymbolAddress((void**)&Qhi, g_Qhi);   cudaGetSymbolAddress((void**)&Qlo, g_Qlo);
    cudaGetSymbolAddress((void**)&Khi, g_Khi);   cudaGetSymbolAddress((void**)&Klo, g_Klo);
    cudaGetSymbolAddress((void**)&Vhi, g_Vhi);   cudaGetSymbolAddress((void**)&Vlo, g_Vlo);
    cudaGetSymbolAddress((void**)&Phi, g_Phi);   cudaGetSymbolAddress((void**)&Plo, g_Plo);
    cudaGetSymbolAddress((void**)&Smat, g_S);

    cudaFuncSetAttribute(gemm_nt_mma<0>, cudaFuncAttributeMaxDynamicSharedMemorySize, GSMEM);
    cudaFuncSetAttribute(gemm_nt_mma<2>, cudaFuncAttributeMaxDynamicSharedMemorySize, GSMEM);
    cudaFuncSetAttribute(gemm_nn_mma,    cudaFuncAttributeMaxDynamicSharedMemorySize, GSMEM);

    // 1) fp32 -> bf16 hi/lo conversions
    cvt_pair<<<1024, 256>>>(X,  Xhi,  Xlo,  (long)SEQ * DM / 4);
    cvt_pair<<<512,  256>>>(Wq, Wqhi, Wqlo, (long)DM * DM / 4);
    cvt_pair<<<512,  256>>>(Wk, Wkhi, Wklo, (long)DM * DM / 4);
    cvt_pair<<<512,  256>>>(Wv, Wvhi, Wvlo, (long)DM * DM / 4);

    dim3 blk(512);
    // 2) projections: [SEQ,DM] = X @ W^T, K=DM
    dim3 gp(DM / 128, SEQ / 128);
    gemm_nt_mma<0><<<gp, blk, GSMEM>>>(Xhi, Xlo, Wqhi, Wqlo, nullptr, Qhi, Qlo, DM, DM, DM, DM);
    gemm_nt_mma<0><<<gp, blk, GSMEM>>>(Xhi, Xlo, Wkhi, Wklo, nullptr, Khi, Klo, DM, DM, DM, DM);
    gemm_nt_mma<0><<<gp, blk, GSMEM>>>(Xhi, Xlo, Wvhi, Wvlo, nullptr, Vhi, Vlo, DM, DM, DM, DM);

    // 3) S = Q @ K^T  [SEQ,SEQ], K=DM
    dim3 gs(SEQ / 128, SEQ / 128);
    gemm_nt_mma<2><<<gs, blk, GSMEM>>>(Qhi, Qlo, Khi, Klo, Smat, nullptr, nullptr, DM, DM, DM, SEQ);

    // 4) P = softmax(S / sqrt(DM)) -> bf16 hi/lo
    softmax_bf16<<<SEQ, 256>>>(Smat, Phi, Plo);

    // 5) O = P @ V  [SEQ,DM], K=SEQ (NN)
    dim3 go(DM / 128, SEQ / 128);
    gemm_nn_mma<<<go, blk, GSMEM>>>(Phi, Plo, Vhi, Vlo, O, SEQ, SEQ, DM, DM);
}

// round 5
// speedup vs baseline: 2.9083x; 1.0005x over previous
#include <cuda_runtime.h>
#include <cuda_bf16.h>
#include <cstdint>
#include <math.h>

#define SEQ 8192
#define DM  2048
typedef __nv_bfloat16 bf16;

// ======================= scratch (device globals) =======================
__device__ bf16  g_Xhi[(size_t)SEQ * DM], g_Xlo[(size_t)SEQ * DM];
__device__ bf16  g_Wqhi[(size_t)DM * DM], g_Wqlo[(size_t)DM * DM];
__device__ bf16  g_Wkhi[(size_t)DM * DM], g_Wklo[(size_t)DM * DM];
__device__ bf16  g_Wvhi[(size_t)DM * DM], g_Wvlo[(size_t)DM * DM];
__device__ bf16  g_Qhi[(size_t)SEQ * DM], g_Qlo[(size_t)SEQ * DM];
__device__ bf16  g_Khi[(size_t)SEQ * DM], g_Klo[(size_t)SEQ * DM];
__device__ bf16  g_Vhi[(size_t)SEQ * DM], g_Vlo[(size_t)SEQ * DM];
__device__ float g_S[(size_t)SEQ * SEQ];
__device__ bf16  g_Phi[(size_t)SEQ * SEQ], g_Plo[(size_t)SEQ * SEQ];

// ======================= helpers =======================
__device__ __forceinline__ uint32_t smem_u32(const void* p) {
    uint32_t a;
    asm("{ .reg .u64 t; cvta.to.shared.u64 t, %1; cvt.u32.u64 %0, t; }" : "=r"(a) : "l"(p));
    return a;
}
#define CP16(sm, gp) \
    asm volatile("cp.async.cg.shared.global [%0], [%1], 16;" :: "r"(sm), "l"(gp))
#define CP_COMMIT() asm volatile("cp.async.commit_group;")
#define CP_WAIT(n)  asm volatile("cp.async.wait_group %0;" :: "n"(n) : "memory")

__device__ __forceinline__ void ldsm_x4(uint32_t* r, uint32_t a) {
    asm volatile("ldmatrix.sync.aligned.m8n8.x4.shared.b16 {%0,%1,%2,%3}, [%4];"
        : "=r"(r[0]), "=r"(r[1]), "=r"(r[2]), "=r"(r[3]) : "r"(a));
}
__device__ __forceinline__ void ldsm_x4_t(uint32_t* r, uint32_t a) {
    asm volatile("ldmatrix.sync.aligned.m8n8.x4.trans.shared.b16 {%0,%1,%2,%3}, [%4];"
        : "=r"(r[0]), "=r"(r[1]), "=r"(r[2]), "=r"(r[3]) : "r"(a));
}
__device__ __forceinline__ void mma16816(float* c, const uint32_t* a, const uint32_t* b) {
    asm volatile("mma.sync.aligned.m16n8k16.row.col.f32.bf16.bf16.f32 "
        "{%0,%1,%2,%3}, {%4,%5,%6,%7}, {%8,%9}, {%0,%1,%2,%3};"
        : "+f"(c[0]), "+f"(c[1]), "+f"(c[2]), "+f"(c[3])
        : "r"(a[0]), "r"(a[1]), "r"(a[2]), "r"(a[3]), "r"(b[0]), "r"(b[1]));
}
__device__ __forceinline__ uint32_t pack_hi(float v0, float v1, uint32_t& lo) {
    bf16 h0 = __float2bfloat16(v0), h1 = __float2bfloat16(v1);
    bf16 l0 = __float2bfloat16(v0 - __bfloat162float(h0));
    bf16 l1 = __float2bfloat16(v1 - __bfloat162float(h1));
    lo = (uint32_t)__bfloat16_as_ushort(l0) | ((uint32_t)__bfloat16_as_ushort(l1) << 16);
    return (uint32_t)__bfloat16_as_ushort(h0) | ((uint32_t)__bfloat16_as_ushort(h1) << 16);
}

#define STAGE 65536
#define GSMEM (2 * STAGE)

// ======================= NT GEMM: C[M,N] = (Ahi+Alo)[M,K] @ (Bhi+Blo)[N,K]^T =======================
// MODE 0: write Chi/Clo bf16 row-major; MODE 2: write Cf fp32 row-major.
template <int MODE>
__global__ __launch_bounds__(512, 1)
void gemm_nt_mma(const bf16* __restrict__ Ahi, const bf16* __restrict__ Alo,
                 const bf16* __restrict__ Bhi, const bf16* __restrict__ Blo,
                 float* __restrict__ Cf, bf16* __restrict__ Chi, bf16* __restrict__ Clo,
                 int Kdim, long ldA, long ldB, long ldC)
{
    extern __shared__ char sm[];
    const uint32_t sb = smem_u32(sm);
    const int tid = threadIdx.x, wid = tid >> 5, lane = tid & 31;
    const int wm = wid >> 2, wn = wid & 3;
    const long row0 = (long)blockIdx.y * 128, col0 = (long)blockIdx.x * 128;
    const int NC = Kdim / 64;

    // loader: 1024 slots per matrix (128 rows x 8 x 16B chunks); 2 slots/thread
    uint32_t soff[2]; long aoff[2], boff[2];
#pragma unroll
    for (int j = 0; j < 2; j++) {
        int slot = tid + j * 512;
        int r = slot >> 3, c = slot & 7;
        soff[j] = (uint32_t)(r * 128 + ((c ^ (r & 7)) << 4));
        aoff[j] = (row0 + r) * ldA + c * 8;
        boff[j] = (col0 + r) * ldB + c * 8;
    }

    // ldmatrix lane addressing
    const int g = lane >> 3, lr = lane & 7;
    const int arow_b = wm * 32 + (g & 1) * 8 + lr;   // + mf*16
    const int brow_b = wn * 32 + (g & 1) * 8 + lr;   // + np*16
    const int ch_hi = g >> 1;                        // + kstep*2

    float acc[2][4][4];
#pragma unroll
    for (int i = 0; i < 2; i++)
#pragma unroll
        for (int j = 0; j < 4; j++)
#pragma unroll
            for (int q = 0; q < 4; q++) acc[i][j][q] = 0.0f;

#define NT_LOAD(buf, kb) do {                                                  \
    uint32_t s_ = sb + (uint32_t)(buf) * STAGE;                                \
    _Pragma("unroll")                                                          \
    for (int j = 0; j < 2; j++) {                                              \
        CP16(s_ +         soff[j], Ahi + aoff[j] + (kb));                      \
        CP16(s_ + 16384 + soff[j], Alo + aoff[j] + (kb));                      \
        CP16(s_ + 32768 + soff[j], Bhi + boff[j] + (kb));                      \
        CP16(s_ + 49152 + soff[j], Blo + boff[j] + (kb));                      \
    }                                                                          \
    CP_COMMIT();                                                               \
} while (0)

    NT_LOAD(0, 0);

    for (int i = 0; i < NC; i++) {
        if (i + 1 < NC) { NT_LOAD((i + 1) & 1, (long)(i + 1) * 64); CP_WAIT(1); }
        else            { CP_WAIT(0); }
        __syncthreads();
        const uint32_t As = sb + (uint32_t)(i & 1) * STAGE;
        const uint32_t Bs = As + 32768;

#pragma unroll
        for (int ks = 0; ks < 4; ks++) {
            uint32_t a[2][2][4], b[2][4][2];
#pragma unroll
            for (int comp = 0; comp < 2; comp++) {
#pragma unroll
                for (int mf = 0; mf < 2; mf++) {
                    int row = arow_b + mf * 16;
                    int ch = ks * 2 + ch_hi;
                    ldsm_x4(a[comp][mf], As + comp * 16384u + row * 128 + ((ch ^ (row & 7)) << 4));
                }
#pragma unroll
                for (int np = 0; np < 2; np++) {
                    int row = brow_b + np * 16;
                    int ch = ks * 2 + ch_hi;
                    uint32_t q[4];
                    ldsm_x4(q, Bs + comp * 16384u + row * 128 + ((ch ^ (row & 7)) << 4));
                    b[comp][np * 2][0]     = q[0]; b[comp][np * 2][1]     = q[2];
                    b[comp][np * 2 + 1][0] = q[1]; b[comp][np * 2 + 1][1] = q[3];
                }
            }
#pragma unroll
            for (int mf = 0; mf < 2; mf++)
#pragma unroll
                for (int nf = 0; nf < 4; nf++) {
                    mma16816(acc[mf][nf], a[0][mf], b[0][nf]);  // hi*hi
                    mma16816(acc[mf][nf], a[0][mf], b[1][nf]);  // hi*lo
                    mma16816(acc[mf][nf], a[1][mf], b[0][nf]);  // lo*hi
                }
        }
        __syncthreads();
    }

    // epilogue
#pragma unroll
    for (int mf = 0; mf < 2; mf++)
#pragma unroll
        for (int nf = 0; nf < 4; nf++) {
            long row = row0 + wm * 32 + mf * 16 + (lane >> 2);
            long col = col0 + wn * 32 + nf * 8 + (lane & 3) * 2;
            if (MODE == 2) {
                *(float2*)(Cf + row * ldC + col)       = make_float2(acc[mf][nf][0], acc[mf][nf][1]);
                *(float2*)(Cf + (row + 8) * ldC + col) = make_float2(acc[mf][nf][2], acc[mf][nf][3]);
            } else {
                uint32_t lo0, lo1;
                uint32_t hi0 = pack_hi(acc[mf][nf][0], acc[mf][nf][1], lo0);
                uint32_t hi1 = pack_hi(acc[mf][nf][2], acc[mf][nf][3], lo1);
                *(uint32_t*)(Chi + row * ldC + col)       = hi0;
                *(uint32_t*)(Clo + row * ldC + col)       = lo0;
                *(uint32_t*)(Chi + (row + 8) * ldC + col) = hi1;
                *(uint32_t*)(Clo + (row + 8) * ldC + col) = lo1;
            }
        }
#undef NT_LOAD
}

// ======================= NN GEMM: C[M,N] = (Ahi+Alo)[M,K] @ (Bhi+Blo)[K,N] =======================
// fp32 output. A k-contiguous (128B row-chunks), B n-contiguous (256B row-chunks).
__global__ __launch_bounds__(512, 1)
void gemm_nn_mma(const bf16* __restrict__ Ahi, const bf16* __restrict__ Alo,
                 const bf16* __restrict__ Bhi, const bf16* __restrict__ Blo,
                 float* __restrict__ Cf, int Kdim, long ldA, long ldB, long ldC)
{
    extern __shared__ char sm[];
    const uint32_t sb = smem_u32(sm);
    const int tid = threadIdx.x, wid = tid >> 5, lane = tid & 31;
    const int wm = wid >> 2, wn = wid & 3;
    const long row0 = (long)blockIdx.y * 128, col0 = (long)blockIdx.x * 128;
    const int NC = Kdim / 64;

    // A loader: 1024 slots (128 rows x 8 chunks); B loader: 1024 slots (64 k-rows x 16 chunks)
    uint32_t soffA[2], soffB[2]; long aoff[2], boff[2];
#pragma unroll
    for (int j = 0; j < 2; j++) {
        int slot = tid + j * 512;
        int ra = slot >> 3, ca = slot & 7;
        soffA[j] = (uint32_t)(ra * 128 + ((ca ^ (ra & 7)) << 4));
        aoff[j]  = (row0 + ra) * ldA + ca * 8;
        int rb = slot >> 4, cb = slot & 15;
        soffB[j] = (uint32_t)(rb * 256 + ((cb ^ (rb & 7)) << 4));
        boff[j]  = (long)rb * ldB + col0 + cb * 8;
    }

    const int g = lane >> 3, lr = lane & 7;
    const int arow_b = wm * 32 + (g & 1) * 8 + lr;       // + mf*16
    const int krow_b = (g & 1) * 8 + lr;                 // + ks*16
    const int bch_b  = wn * 4 + (g >> 1);                // + np*2

    float acc[2][4][4];
#pragma unroll
    for (int i = 0; i < 2; i++)
#pragma unroll
        for (int j = 0; j < 4; j++)
#pragma unroll
            for (int q = 0; q < 4; q++) acc[i][j][q] = 0.0f;

#define NN_LOAD(buf, kb) do {                                                  \
    uint32_t s_ = sb + (uint32_t)(buf) * STAGE;                                \
    long kb_ = (kb);                                                           \
    _Pragma("unroll")                                                          \
    for (int j = 0; j < 2; j++) {                                              \
        CP16(s_ +         soffA[j], Ahi + aoff[j] + kb_);                      \
        CP16(s_ + 16384 + soffA[j], Alo + aoff[j] + kb_);                      \
        CP16(s_ + 32768 + soffB[j], Bhi + boff[j] + kb_ * ldB);                \
        CP16(s_ + 49152 + soffB[j], Blo + boff[j] + kb_ * ldB);                \
    }                                                                          \
    CP_COMMIT();                                                               \
} while (0)

    NN_LOAD(0, 0);

    for (int i = 0; i < NC; i++) {
        if (i + 1 < NC) { NN_LOAD((i + 1) & 1, (long)(i + 1) * 64); CP_WAIT(1); }
        else            { CP_WAIT(0); }
        __syncthreads();
        const uint32_t As = sb + (uint32_t)(i & 1) * STAGE;
        const uint32_t Bs = As + 32768;

#pragma unroll
        for (int ks = 0; ks < 4; ks++) {
            uint32_t a[2][2][4], b[2][4][2];
#pragma unroll
            for (int comp = 0; comp < 2; comp++) {
#pragma unroll
                for (int mf = 0; mf < 2; mf++) {
                    int row = arow_b + mf * 16;
                    int ch = ks * 2 + (g >> 1);
                    ldsm_x4(a[comp][mf], As + comp * 16384u + row * 128 + ((ch ^ (row & 7)) << 4));
                }
#pragma unroll
                for (int np = 0; np < 2; np++) {
                    int krow = krow_b + ks * 16;
                    int ch = bch_b + np * 2;
                    uint32_t q[4];
                    ldsm_x4_t(q, Bs + comp * 16384u + krow * 256 + ((ch ^ (krow & 7)) << 4));
                    b[comp][np * 2][0]     = q[0]; b[comp][np * 2][1]     = q[1];
                    b[comp][np * 2 + 1][0] = q[2]; b[comp][np * 2 + 1][1] = q[3];
                }
            }
#pragma unroll
            for (int mf = 0; mf < 2; mf++)
#pragma unroll
                for (int nf = 0; nf < 4; nf++) {
                    mma16816(acc[mf][nf], a[0][mf], b[0][nf]);
                    mma16816(acc[mf][nf], a[0][mf], b[1][nf]);
                    mma16816(acc[mf][nf], a[1][mf], b[0][nf]);
                }
        }
        __syncthreads();
    }

#pragma unroll
    for (int mf = 0; mf < 2; mf++)
#pragma unroll
        for (int nf = 0; nf < 4; nf++) {
            long row = row0 + wm * 32 + mf * 16 + (lane >> 2);
            long col = col0 + wn * 32 + nf * 8 + (lane & 3) * 2;
            *(float2*)(Cf + row * ldC + col)       = make_float2(acc[mf][nf][0], acc[mf][nf][1]);
            *(float2*)(Cf + (row + 8) * ldC + col) = make_float2(acc[mf][nf][2], acc[mf][nf][3]);
        }
#undef NN_LOAD
}

// ======================= fp32 -> bf16 hi/lo conversion =======================
__global__ __launch_bounds__(256)
void cvt_pair(const float* __restrict__ s, bf16* __restrict__ hi, bf16* __restrict__ lo, long n4)
{
    for (long i = blockIdx.x * 256 + threadIdx.x; i < n4; i += (long)gridDim.x * 256) {
        float4 v = ((const float4*)s)[i];
        uint32_t l0, l1;
        uint32_t h0 = pack_hi(v.x, v.y, l0);
        uint32_t h1 = pack_hi(v.z, v.w, l1);
        ((uint2*)hi)[i] = make_uint2(h0, h1);
        ((uint2*)lo)[i] = make_uint2(l0, l1);
    }
}

// ======================= row softmax S -> P (bf16 hi/lo) =======================
__global__ __launch_bounds__(256)
void softmax_bf16(const float* __restrict__ S, bf16* __restrict__ Phi, bf16* __restrict__ Plo)
{
    const long row = blockIdx.x;
    const float4* rp = (const float4*)(S + row * (long)SEQ);
    const int tid = threadIdx.x;
    const float scale = 0.02209708691207961f;  // 1/sqrt(2048)

    float4 v[8];
    float mx = -INFINITY;
#pragma unroll
    for (int i = 0; i < 8; i++) {
        v[i] = rp[tid + i * 256];
        mx = fmaxf(mx, fmaxf(fmaxf(v[i].x, v[i].y), fmaxf(v[i].z, v[i].w)));
    }

    __shared__ float red[256];
    red[tid] = mx;
    __syncthreads();
    for (int s = 128; s > 0; s >>= 1) {
        if (tid < s) red[tid] = fmaxf(red[tid], red[tid + s]);
        __syncthreads();
    }
    mx = red[0];
    __syncthreads();

    float sum = 0.0f;
#pragma unroll
    for (int i = 0; i < 8; i++) {
        v[i].x = __expf((v[i].x - mx) * scale);
        v[i].y = __expf((v[i].y - mx) * scale);
        v[i].z = __expf((v[i].z - mx) * scale);
        v[i].w = __expf((v[i].w - mx) * scale);
        sum += (v[i].x + v[i].y) + (v[i].z + v[i].w);
    }
    red[tid] = sum;
    __syncthreads();
    for (int s = 128; s > 0; s >>= 1) {
        if (tid < s) red[tid] += red[tid + s];
        __syncthreads();
    }
    const float inv = 1.0f / red[0];

#pragma unroll
    for (int i = 0; i < 8; i++) {
        uint32_t l0, l1;
        uint32_t h0 = pack_hi(v[i].x * inv, v[i].y * inv, l0);
        uint32_t h1 = pack_hi(v[i].z * inv, v[i].w * inv, l1);
        long idx = row * (long)SEQ + (long)(tid + i * 256) * 4;
        ((uint2*)(Phi + idx))[0] = make_uint2(h0, h1);
        ((uint2*)(Plo + idx))[0] = make_uint2(l0, l1);
    }
}

// ======================= launch =======================
extern "C" void kernel_launch(void* const* d_in, const int* in_sizes, int n_in,
                              void* d_out, int out_size)
{
    (void)in_sizes; (void)n_in; (void)out_size;
    const float* X  = (const float*)d_in[0];
    const float* Wq = (const float*)d_in[1];
    const float* Wk = (const float*)d_in[2];
    const float* Wv = (const float*)d_in[3];
    float* O = (float*)d_out;

    bf16 *Xhi, *Xlo, *Wqhi, *Wqlo, *Wkhi, *Wklo, *Wvhi, *Wvlo;
    bf16 *Qhi, *Qlo, *Khi, *Klo, *Vhi, *Vlo, *Phi, *Plo;
    float* Smat;
    cudaGetSymbolAddress((void**)&Xhi, g_Xhi);   cudaGetSymbolAddress((void**)&Xlo, g_Xlo);
    cudaGetSymbolAddress((void**)&Wqhi, g_Wqhi); cudaGetSymbolAddress((void**)&Wqlo, g_Wqlo);
    cudaGetSymbolAddress((void**)&Wkhi, g_Wkhi); cudaGetSymbolAddress((void**)&Wklo, g_Wklo);
    cudaGetSymbolAddress((void**)&Wvhi, g_Wvhi); cudaGetSymbolAddress((void**)&Wvlo, g_Wvlo);
    cudaGetSymbolAddress((void**)&Qhi, g_Qhi);   cudaGetSymbolAddress((void**)&Qlo, g_Qlo);
    cudaGetSymbolAddress((void**)&Khi, g_Khi);   cudaGetSymbolAddress((void**)&Klo, g_Klo);
    cudaGetSymbolAddress((void**)&Vhi, g_Vhi);   cudaGetSymbolAddress((void**)&Vlo, g_Vlo);
    cudaGetSymbolAddress((void**)&Phi, g_Phi);   cudaGetSymbolAddress((void**)&Plo, g_Plo);
    cudaGetSymbolAddress((void**)&Smat, g_S);

    cudaFuncSetAttribute(gemm_nt_mma<0>, cudaFuncAttributeMaxDynamicSharedMemorySize, GSMEM);
    cudaFuncSetAttribute(gemm_nt_mma<2>, cudaFuncAttributeMaxDynamicSharedMemorySize, GSMEM);
    cudaFuncSetAttribute(gemm_nn_mma,    cudaFuncAttributeMaxDynamicSharedMemorySize, GSMEM);

    // 1) fp32 -> bf16 hi/lo conversions
    cvt_pair<<<1024, 256>>>(X,  Xhi,  Xlo,  (long)SEQ * DM / 4);
    cvt_pair<<<512,  256>>>(Wq, Wqhi, Wqlo, (long)DM * DM / 4);
    cvt_pair<<<512,  256>>>(Wk, Wkhi, Wklo, (long)DM * DM / 4);
    cvt_pair<<<512,  256>>>(Wv, Wvhi, Wvlo, (long)DM * DM / 4);

    dim3 blk(512);
    // 2) projections: [SEQ,DM] = X @ W^T, K=DM
    dim3 gp(DM / 128, SEQ / 128);
    gemm_nt_mma<0><<<gp, blk, GSMEM>>>(Xhi, Xlo, Wqhi, Wqlo, nullptr, Qhi, Qlo, DM, DM, DM, DM);
    gemm_nt_mma<0><<<gp, blk, GSMEM>>>(Xhi, Xlo, Wkhi, Wklo, nullptr, Khi, Klo, DM, DM, DM, DM);
    gemm_nt_mma<0><<<gp, blk, GSMEM>>>(Xhi, Xlo, Wvhi, Wvlo, nullptr, Vhi, Vlo, DM, DM, DM, DM);

    // 3) S = Q @ K^T  [SEQ,SEQ], K=DM
    dim3 gs(SEQ / 128, SEQ / 128);
    gemm_nt_mma<2><<<gs, blk, GSMEM>>>(Qhi, Qlo, Khi, Klo, Smat, nullptr, nullptr, DM, DM, DM, SEQ);

    // 4) P = softmax(S / sqrt(DM)) -> bf16 hi/lo
    softmax_bf16<<<SEQ, 256>>>(Smat, Phi, Plo);

    // 5) O = P @ V  [SEQ,DM], K=SEQ (NN)
    dim3 go(DM / 128, SEQ / 128);
    gemm_nn_mma<<<go, blk, GSMEM>>>(Phi, Plo, Vhi, Vlo, O, SEQ, SEQ, DM, DM);
}

// round 6
// speedup vs baseline: 3.6066x; 1.2401x over previous
#include <cuda_runtime.h>
#include <cuda_bf16.h>
#include <cuda_fp16.h>
#include <cstdint>
#include <math.h>

#define SEQ 8192
#define DM  2048
typedef __nv_bfloat16 bf16;

// ======================= scratch (device globals) =======================
__device__ bf16   g_Xhi[(size_t)SEQ * DM], g_Xlo[(size_t)SEQ * DM];
__device__ bf16   g_Wqhi[(size_t)DM * DM], g_Wqlo[(size_t)DM * DM];
__device__ bf16   g_Wkhi[(size_t)DM * DM], g_Wklo[(size_t)DM * DM];
__device__ bf16   g_Wvhi[(size_t)DM * DM], g_Wvlo[(size_t)DM * DM];
__device__ bf16   g_Qhi[(size_t)SEQ * DM], g_Qlo[(size_t)SEQ * DM];
__device__ bf16   g_Khi[(size_t)SEQ * DM], g_Klo[(size_t)SEQ * DM];
__device__ __half g_V16[(size_t)SEQ * DM];
__device__ float  g_S[(size_t)SEQ * SEQ];
__device__ __half g_P16[(size_t)SEQ * SEQ];

// ======================= helpers =======================
__device__ __forceinline__ uint32_t smem_u32(const void* p) {
    uint32_t a;
    asm("{ .reg .u64 t; cvta.to.shared.u64 t, %1; cvt.u32.u64 %0, t; }" : "=r"(a) : "l"(p));
    return a;
}
#define CP16(sm, gp) \
    asm volatile("cp.async.cg.shared.global [%0], [%1], 16;" :: "r"(sm), "l"(gp))
#define CP_COMMIT() asm volatile("cp.async.commit_group;")
#define CP_WAIT(n)  asm volatile("cp.async.wait_group %0;" :: "n"(n) : "memory")

__device__ __forceinline__ void ldsm_x4(uint32_t* r, uint32_t a) {
    asm volatile("ldmatrix.sync.aligned.m8n8.x4.shared.b16 {%0,%1,%2,%3}, [%4];"
        : "=r"(r[0]), "=r"(r[1]), "=r"(r[2]), "=r"(r[3]) : "r"(a));
}
__device__ __forceinline__ void ldsm_x4_t(uint32_t* r, uint32_t a) {
    asm volatile("ldmatrix.sync.aligned.m8n8.x4.trans.shared.b16 {%0,%1,%2,%3}, [%4];"
        : "=r"(r[0]), "=r"(r[1]), "=r"(r[2]), "=r"(r[3]) : "r"(a));
}
__device__ __forceinline__ void mma16816(float* c, const uint32_t* a, const uint32_t* b) {
    asm volatile("mma.sync.aligned.m16n8k16.row.col.f32.bf16.bf16.f32 "
        "{%0,%1,%2,%3}, {%4,%5,%6,%7}, {%8,%9}, {%0,%1,%2,%3};"
        : "+f"(c[0]), "+f"(c[1]), "+f"(c[2]), "+f"(c[3])
        : "r"(a[0]), "r"(a[1]), "r"(a[2]), "r"(a[3]), "r"(b[0]), "r"(b[1]));
}
__device__ __forceinline__ void mma16816h(float* c, const uint32_t* a, const uint32_t* b) {
    asm volatile("mma.sync.aligned.m16n8k16.row.col.f32.f16.f16.f32 "
        "{%0,%1,%2,%3}, {%4,%5,%6,%7}, {%8,%9}, {%0,%1,%2,%3};"
        : "+f"(c[0]), "+f"(c[1]), "+f"(c[2]), "+f"(c[3])
        : "r"(a[0]), "r"(a[1]), "r"(a[2]), "r"(a[3]), "r"(b[0]), "r"(b[1]));
}
__device__ __forceinline__ uint32_t pack_hi(float v0, float v1, uint32_t& lo) {
    bf16 h0 = __float2bfloat16(v0), h1 = __float2bfloat16(v1);
    bf16 l0 = __float2bfloat16(v0 - __bfloat162float(h0));
    bf16 l1 = __float2bfloat16(v1 - __bfloat162float(h1));
    lo = (uint32_t)__bfloat16_as_ushort(l0) | ((uint32_t)__bfloat16_as_ushort(l1) << 16);
    return (uint32_t)__bfloat16_as_ushort(h0) | ((uint32_t)__bfloat16_as_ushort(h1) << 16);
}
__device__ __forceinline__ uint32_t pack_h2(float a, float b) {
    __half2 h = __floats2half2_rn(a, b);
    return *(uint32_t*)&h;
}

#define STAGE 65536
#define GSMEM (2 * STAGE)

// ======================= NT GEMM: C[M,N] = (Ahi+Alo)[M,K] @ (Bhi+Blo)[N,K]^T =======================
// MODE 0: bf16 hi/lo pair out; MODE 2: fp32 out; MODE 3: single fp16 out.
template <int MODE>
__global__ __launch_bounds__(512, 1)
void gemm_nt_mma(const bf16* __restrict__ Ahi, const bf16* __restrict__ Alo,
                 const bf16* __restrict__ Bhi, const bf16* __restrict__ Blo,
                 float* __restrict__ Cf, bf16* __restrict__ Chi, bf16* __restrict__ Clo,
                 __half* __restrict__ C16,
                 int Kdim, long ldA, long ldB, long ldC)
{
    extern __shared__ char sm[];
    const uint32_t sb = smem_u32(sm);
    const int tid = threadIdx.x, wid = tid >> 5, lane = tid & 31;
    const int wm = wid >> 2, wn = wid & 3;
    const long row0 = (long)blockIdx.y * 128, col0 = (long)blockIdx.x * 128;
    const int NC = Kdim / 64;

    uint32_t soff[2]; long aoff[2], boff[2];
#pragma unroll
    for (int j = 0; j < 2; j++) {
        int slot = tid + j * 512;
        int r = slot >> 3, c = slot & 7;
        soff[j] = (uint32_t)(r * 128 + ((c ^ (r & 7)) << 4));
        aoff[j] = (row0 + r) * ldA + c * 8;
        boff[j] = (col0 + r) * ldB + c * 8;
    }

    const int g = lane >> 3, lr = lane & 7;
    const int arow_b = wm * 32 + (g & 1) * 8 + lr;
    const int brow_b = wn * 32 + (g & 1) * 8 + lr;
    const int ch_hi = g >> 1;

    float acc[2][4][4];
#pragma unroll
    for (int i = 0; i < 2; i++)
#pragma unroll
        for (int j = 0; j < 4; j++)
#pragma unroll
            for (int q = 0; q < 4; q++) acc[i][j][q] = 0.0f;

#define NT_LOAD(buf, kb) do {                                                  \
    uint32_t s_ = sb + (uint32_t)(buf) * STAGE;                                \
    _Pragma("unroll")                                                          \
    for (int j = 0; j < 2; j++) {                                              \
        CP16(s_ +         soff[j], Ahi + aoff[j] + (kb));                      \
        CP16(s_ + 16384 + soff[j], Alo + aoff[j] + (kb));                      \
        CP16(s_ + 32768 + soff[j], Bhi + boff[j] + (kb));                      \
        CP16(s_ + 49152 + soff[j], Blo + boff[j] + (kb));                      \
    }                                                                          \
    CP_COMMIT();                                                               \
} while (0)

    NT_LOAD(0, 0);

    for (int i = 0; i < NC; i++) {
        if (i + 1 < NC) { NT_LOAD((i + 1) & 1, (long)(i + 1) * 64); CP_WAIT(1); }
        else            { CP_WAIT(0); }
        __syncthreads();
        const uint32_t As = sb + (uint32_t)(i & 1) * STAGE;
        const uint32_t Bs = As + 32768;

#pragma unroll
        for (int ks = 0; ks < 4; ks++) {
            uint32_t a[2][2][4], b[2][4][2];
#pragma unroll
            for (int comp = 0; comp < 2; comp++) {
#pragma unroll
                for (int mf = 0; mf < 2; mf++) {
                    int row = arow_b + mf * 16;
                    int ch = ks * 2 + ch_hi;
                    ldsm_x4(a[comp][mf], As + comp * 16384u + row * 128 + ((ch ^ (row & 7)) << 4));
                }
#pragma unroll
                for (int np = 0; np < 2; np++) {
                    int row = brow_b + np * 16;
                    int ch = ks * 2 + ch_hi;
                    uint32_t q[4];
                    ldsm_x4(q, Bs + comp * 16384u + row * 128 + ((ch ^ (row & 7)) << 4));
                    b[comp][np * 2][0]     = q[0]; b[comp][np * 2][1]     = q[2];
                    b[comp][np * 2 + 1][0] = q[1]; b[comp][np * 2 + 1][1] = q[3];
                }
            }
#pragma unroll
            for (int mf = 0; mf < 2; mf++)
#pragma unroll
                for (int nf = 0; nf < 4; nf++) {
                    mma16816(acc[mf][nf], a[0][mf], b[0][nf]);
                    mma16816(acc[mf][nf], a[0][mf], b[1][nf]);
                    mma16816(acc[mf][nf], a[1][mf], b[0][nf]);
                }
        }
        __syncthreads();
    }

#pragma unroll
    for (int mf = 0; mf < 2; mf++)
#pragma unroll
        for (int nf = 0; nf < 4; nf++) {
            long row = row0 + wm * 32 + mf * 16 + (lane >> 2);
            long col = col0 + wn * 32 + nf * 8 + (lane & 3) * 2;
            if (MODE == 2) {
                *(float2*)(Cf + row * ldC + col)       = make_float2(acc[mf][nf][0], acc[mf][nf][1]);
                *(float2*)(Cf + (row + 8) * ldC + col) = make_float2(acc[mf][nf][2], acc[mf][nf][3]);
            } else if (MODE == 3) {
                *(uint32_t*)(C16 + row * ldC + col)       = pack_h2(acc[mf][nf][0], acc[mf][nf][1]);
                *(uint32_t*)(C16 + (row + 8) * ldC + col) = pack_h2(acc[mf][nf][2], acc[mf][nf][3]);
            } else {
                uint32_t lo0, lo1;
                uint32_t hi0 = pack_hi(acc[mf][nf][0], acc[mf][nf][1], lo0);
                uint32_t hi1 = pack_hi(acc[mf][nf][2], acc[mf][nf][3], lo1);
                *(uint32_t*)(Chi + row * ldC + col)       = hi0;
                *(uint32_t*)(Clo + row * ldC + col)       = lo0;
                *(uint32_t*)(Chi + (row + 8) * ldC + col) = hi1;
                *(uint32_t*)(Clo + (row + 8) * ldC + col) = lo1;
            }
        }
#undef NT_LOAD
}

// ======================= NN GEMM (fp16 single-term): C[M,N] = A[M,K] @ B[K,N] =======================
#define STAGE_NN 32768
#define GSMEM_NN (2 * STAGE_NN)
__global__ __launch_bounds__(512, 1)
void gemm_nn_f16(const __half* __restrict__ A, const __half* __restrict__ B,
                 float* __restrict__ Cf, int Kdim, long ldA, long ldB, long ldC)
{
    extern __shared__ char sm[];
    const uint32_t sb = smem_u32(sm);
    const int tid = threadIdx.x, wid = tid >> 5, lane = tid & 31;
    const int wm = wid >> 2, wn = wid & 3;
    const long row0 = (long)blockIdx.y * 128, col0 = (long)blockIdx.x * 128;
    const int NC = Kdim / 64;

    uint32_t soffA[2], soffB[2]; long aoff[2], boff[2];
#pragma unroll
    for (int j = 0; j < 2; j++) {
        int slot = tid + j * 512;
        int ra = slot >> 3, ca = slot & 7;
        soffA[j] = (uint32_t)(ra * 128 + ((ca ^ (ra & 7)) << 4));
        aoff[j]  = (row0 + ra) * ldA + ca * 8;
        int rb = slot >> 4, cb = slot & 15;
        soffB[j] = (uint32_t)(rb * 256 + ((cb ^ (rb & 7)) << 4));
        boff[j]  = (long)rb * ldB + col0 + cb * 8;
    }

    const int g = lane >> 3, lr = lane & 7;
    const int arow_b = wm * 32 + (g & 1) * 8 + lr;
    const int krow_b = (g & 1) * 8 + lr;
    const int bch_b  = wn * 4 + (g >> 1);

    float acc[2][4][4];
#pragma unroll
    for (int i = 0; i < 2; i++)
#pragma unroll
        for (int j = 0; j < 4; j++)
#pragma unroll
            for (int q = 0; q < 4; q++) acc[i][j][q] = 0.0f;

#define NN_LOAD(buf, kb) do {                                                  \
    uint32_t s_ = sb + (uint32_t)(buf) * STAGE_NN;                             \
    long kb_ = (kb);                                                           \
    _Pragma("unroll")                                                          \
    for (int j = 0; j < 2; j++) {                                              \
        CP16(s_ +         soffA[j], A + aoff[j] + kb_);                        \
        CP16(s_ + 16384 + soffB[j], B + boff[j] + kb_ * ldB);                  \
    }                                                                          \
    CP_COMMIT();                                                               \
} while (0)

    NN_LOAD(0, 0);

    for (int i = 0; i < NC; i++) {
        if (i + 1 < NC) { NN_LOAD((i + 1) & 1, (long)(i + 1) * 64); CP_WAIT(1); }
        else            { CP_WAIT(0); }
        __syncthreads();
        const uint32_t As = sb + (uint32_t)(i & 1) * STAGE_NN;
        const uint32_t Bs = As + 16384;

#pragma unroll
        for (int ks = 0; ks < 4; ks++) {
            uint32_t a[2][4], b[4][2];
#pragma unroll
            for (int mf = 0; mf < 2; mf++) {
                int row = arow_b + mf * 16;
                int ch = ks * 2 + (g >> 1);
                ldsm_x4(a[mf], As + row * 128 + ((ch ^ (row & 7)) << 4));
            }
#pragma unroll
            for (int np = 0; np < 2; np++) {
                int krow = krow_b + ks * 16;
                int ch = bch_b + np * 2;
                uint32_t q[4];
                ldsm_x4_t(q, Bs + krow * 256 + ((ch ^ (krow & 7)) << 4));
                b[np * 2][0]     = q[0]; b[np * 2][1]     = q[1];
                b[np * 2 + 1][0] = q[2]; b[np * 2 + 1][1] = q[3];
            }
#pragma unroll
            for (int mf = 0; mf < 2; mf++)
#pragma unroll
                for (int nf = 0; nf < 4; nf++)
                    mma16816h(acc[mf][nf], a[mf], b[nf]);
        }
        __syncthreads();
    }

#pragma unroll
    for (int mf = 0; mf < 2; mf++)
#pragma unroll
        for (int nf = 0; nf < 4; nf++) {
            long row = row0 + wm * 32 + mf * 16 + (lane >> 2);
            long col = col0 + wn * 32 + nf * 8 + (lane & 3) * 2;
            *(float2*)(Cf + row * ldC + col)       = make_float2(acc[mf][nf][0], acc[mf][nf][1]);
            *(float2*)(Cf + (row + 8) * ldC + col) = make_float2(acc[mf][nf][2], acc[mf][nf][3]);
        }
#undef NN_LOAD
}

// ======================= fp32 -> bf16 hi/lo conversion =======================
__global__ __launch_bounds__(256)
void cvt_pair(const float* __restrict__ s, bf16* __restrict__ hi, bf16* __restrict__ lo, long n4)
{
    for (long i = blockIdx.x * 256 + threadIdx.x; i < n4; i += (long)gridDim.x * 256) {
        float4 v = ((const float4*)s)[i];
        uint32_t l0, l1;
        uint32_t h0 = pack_hi(v.x, v.y, l0);
        uint32_t h1 = pack_hi(v.z, v.w, l1);
        ((uint2*)hi)[i] = make_uint2(h0, h1);
        ((uint2*)lo)[i] = make_uint2(l0, l1);
    }
}

// ======================= row softmax S -> P (fp16) =======================
__global__ __launch_bounds__(256)
void softmax_f16(const float* __restrict__ S, __half* __restrict__ P)
{
    const long row = blockIdx.x;
    const float4* rp = (const float4*)(S + row * (long)SEQ);
    const int tid = threadIdx.x;
    const float scale = 0.02209708691207961f;  // 1/sqrt(2048)

    float4 v[8];
    float mx = -INFINITY;
#pragma unroll
    for (int i = 0; i < 8; i++) {
        v[i] = rp[tid + i * 256];
        mx = fmaxf(mx, fmaxf(fmaxf(v[i].x, v[i].y), fmaxf(v[i].z, v[i].w)));
    }

    __shared__ float red[256];
    red[tid] = mx;
    __syncthreads();
    for (int s = 128; s > 0; s >>= 1) {
        if (tid < s) red[tid] = fmaxf(red[tid], red[tid + s]);
        __syncthreads();
    }
    mx = red[0];
    __syncthreads();

    float sum = 0.0f;
#pragma unroll
    for (int i = 0; i < 8; i++) {
        v[i].x = __expf((v[i].x - mx) * scale);
        v[i].y = __expf((v[i].y - mx) * scale);
        v[i].z = __expf((v[i].z - mx) * scale);
        v[i].w = __expf((v[i].w - mx) * scale);
        sum += (v[i].x + v[i].y) + (v[i].z + v[i].w);
    }
    red[tid] = sum;
    __syncthreads();
    for (int s = 128; s > 0; s >>= 1) {
        if (tid < s) red[tid] += red[tid + s];
        __syncthreads();
    }
    const float inv = 1.0f / red[0];

#pragma unroll
    for (int i = 0; i < 8; i++) {
        long idx = row * (long)SEQ + (long)(tid + i * 256) * 4;
        ((uint2*)(P + idx))[0] = make_uint2(pack_h2(v[i].x * inv, v[i].y * inv),
                                            pack_h2(v[i].z * inv, v[i].w * inv));
    }
}

// ======================= launch =======================
extern "C" void kernel_launch(void* const* d_in, const int* in_sizes, int n_in,
                              void* d_out, int out_size)
{
    (void)in_sizes; (void)n_in; (void)out_size;
    const float* X  = (const float*)d_in[0];
    const float* Wq = (const float*)d_in[1];
    const float* Wk = (const float*)d_in[2];
    const float* Wv = (const float*)d_in[3];
    float* O = (float*)d_out;

    bf16 *Xhi, *Xlo, *Wqhi, *Wqlo, *Wkhi, *Wklo, *Wvhi, *Wvlo;
    bf16 *Qhi, *Qlo, *Khi, *Klo;
    __half *V16, *P16;
    float* Smat;
    cudaGetSymbolAddress((void**)&Xhi, g_Xhi);   cudaGetSymbolAddress((void**)&Xlo, g_Xlo);
    cudaGetSymbolAddress((void**)&Wqhi, g_Wqhi); cudaGetSymbolAddress((void**)&Wqlo, g_Wqlo);
    cudaGetSymbolAddress((void**)&Wkhi, g_Wkhi); cudaGetSymbolAddress((void**)&Wklo, g_Wklo);
    cudaGetSymbolAddress((void**)&Wvhi, g_Wvhi); cudaGetSymbolAddress((void**)&Wvlo, g_Wvlo);
    cudaGetSymbolAddress((void**)&Qhi, g_Qhi);   cudaGetSymbolAddress((void**)&Qlo, g_Qlo);
    cudaGetSymbolAddress((void**)&Khi, g_Khi);   cudaGetSymbolAddress((void**)&Klo, g_Klo);
    cudaGetSymbolAddress((void**)&V16, g_V16);
    cudaGetSymbolAddress((void**)&P16, g_P16);
    cudaGetSymbolAddress((void**)&Smat, g_S);

    cudaFuncSetAttribute(gemm_nt_mma<0>, cudaFuncAttributeMaxDynamicSharedMemorySize, GSMEM);
    cudaFuncSetAttribute(gemm_nt_mma<2>, cudaFuncAttributeMaxDynamicSharedMemorySize, GSMEM);
    cudaFuncSetAttribute(gemm_nt_mma<3>, cudaFuncAttributeMaxDynamicSharedMemorySize, GSMEM);
    cudaFuncSetAttribute(gemm_nn_f16,    cudaFuncAttributeMaxDynamicSharedMemorySize, GSMEM_NN);

    // 1) fp32 -> bf16 hi/lo conversions
    cvt_pair<<<1024, 256>>>(X,  Xhi,  Xlo,  (long)SEQ * DM / 4);
    cvt_pair<<<512,  256>>>(Wq, Wqhi, Wqlo, (long)DM * DM / 4);
    cvt_pair<<<512,  256>>>(Wk, Wkhi, Wklo, (long)DM * DM / 4);
    cvt_pair<<<512,  256>>>(Wv, Wvhi, Wvlo, (long)DM * DM / 4);

    dim3 blk(512);
    // 2) projections: [SEQ,DM] = X @ W^T, K=DM  (Q,K: bf16 pair; V: fp16 single)
    dim3 gp(DM / 128, SEQ / 128);
    gemm_nt_mma<0><<<gp, blk, GSMEM>>>(Xhi, Xlo, Wqhi, Wqlo, nullptr, Qhi, Qlo, nullptr, DM, DM, DM, DM);
    gemm_nt_mma<0><<<gp, blk, GSMEM>>>(Xhi, Xlo, Wkhi, Wklo, nullptr, Khi, Klo, nullptr, DM, DM, DM, DM);
    gemm_nt_mma<3><<<gp, blk, GSMEM>>>(Xhi, Xlo, Wvhi, Wvlo, nullptr, nullptr, nullptr, V16, DM, DM, DM, DM);

    // 3) S = Q @ K^T  [SEQ,SEQ], K=DM (bf16 3-term, fp32 out)
    dim3 gs(SEQ / 128, SEQ / 128);
    gemm_nt_mma<2><<<gs, blk, GSMEM>>>(Qhi, Qlo, Khi, Klo, Smat, nullptr, nullptr, nullptr, DM, DM, DM, SEQ);

    // 4) P = softmax(S / sqrt(DM)) -> fp16
    softmax_f16<<<SEQ, 256>>>(Smat, P16);

    // 5) O = P @ V  [SEQ,DM], K=SEQ (fp16 single-term NN)
    dim3 go(DM / 128, SEQ / 128);
    gemm_nn_f16<<<go, blk, GSMEM_NN>>>(P16, V16, O, SEQ, SEQ, DM, DM);
}

// round 7
// speedup vs baseline: 4.2110x; 1.1676x over previous
#include <cuda_runtime.h>
#include <cuda_bf16.h>
#include <cuda_fp16.h>
#include <cstdint>
#include <math.h>

#define SEQ 8192
#define DM  2048
typedef __nv_bfloat16 bf16;

// ======================= scratch (device globals) =======================
__device__ bf16   g_Xhi[(size_t)SEQ * DM], g_Xlo[(size_t)SEQ * DM];
__device__ bf16   g_Wqhi[(size_t)DM * DM], g_Wqlo[(size_t)DM * DM];
__device__ bf16   g_Wkhi[(size_t)DM * DM], g_Wklo[(size_t)DM * DM];
__device__ bf16   g_Wvhi[(size_t)DM * DM], g_Wvlo[(size_t)DM * DM];
__device__ __half g_Q16[(size_t)SEQ * DM];
__device__ __half g_Khi16[(size_t)SEQ * DM], g_Klo16[(size_t)SEQ * DM];
__device__ __half g_V16[(size_t)SEQ * DM];
__device__ float  g_S[(size_t)SEQ * SEQ];
__device__ __half g_P16[(size_t)SEQ * SEQ];

// ======================= helpers =======================
__device__ __forceinline__ uint32_t smem_u32(const void* p) {
    uint32_t a;
    asm("{ .reg .u64 t; cvta.to.shared.u64 t, %1; cvt.u32.u64 %0, t; }" : "=r"(a) : "l"(p));
    return a;
}
#define CP16(sm, gp) \
    asm volatile("cp.async.cg.shared.global [%0], [%1], 16;" :: "r"(sm), "l"(gp))
#define CP_COMMIT() asm volatile("cp.async.commit_group;")
#define CP_WAIT(n)  asm volatile("cp.async.wait_group %0;" :: "n"(n) : "memory")

__device__ __forceinline__ void ldsm_x4(uint32_t* r, uint32_t a) {
    asm volatile("ldmatrix.sync.aligned.m8n8.x4.shared.b16 {%0,%1,%2,%3}, [%4];"
        : "=r"(r[0]), "=r"(r[1]), "=r"(r[2]), "=r"(r[3]) : "r"(a));
}
__device__ __forceinline__ void ldsm_x4_t(uint32_t* r, uint32_t a) {
    asm volatile("ldmatrix.sync.aligned.m8n8.x4.trans.shared.b16 {%0,%1,%2,%3}, [%4];"
        : "=r"(r[0]), "=r"(r[1]), "=r"(r[2]), "=r"(r[3]) : "r"(a));
}
__device__ __forceinline__ void mma16816(float* c, const uint32_t* a, const uint32_t* b) {
    asm volatile("mma.sync.aligned.m16n8k16.row.col.f32.bf16.bf16.f32 "
        "{%0,%1,%2,%3}, {%4,%5,%6,%7}, {%8,%9}, {%0,%1,%2,%3};"
        : "+f"(c[0]), "+f"(c[1]), "+f"(c[2]), "+f"(c[3])
        : "r"(a[0]), "r"(a[1]), "r"(a[2]), "r"(a[3]), "r"(b[0]), "r"(b[1]));
}
__device__ __forceinline__ void mma16816h(float* c, const uint32_t* a, const uint32_t* b) {
    asm volatile("mma.sync.aligned.m16n8k16.row.col.f32.f16.f16.f32 "
        "{%0,%1,%2,%3}, {%4,%5,%6,%7}, {%8,%9}, {%0,%1,%2,%3};"
        : "+f"(c[0]), "+f"(c[1]), "+f"(c[2]), "+f"(c[3])
        : "r"(a[0]), "r"(a[1]), "r"(a[2]), "r"(a[3]), "r"(b[0]), "r"(b[1]));
}
__device__ __forceinline__ uint32_t pack_hi(float v0, float v1, uint32_t& lo) {
    bf16 h0 = __float2bfloat16(v0), h1 = __float2bfloat16(v1);
    bf16 l0 = __float2bfloat16(v0 - __bfloat162float(h0));
    bf16 l1 = __float2bfloat16(v1 - __bfloat162float(h1));
    lo = (uint32_t)__bfloat16_as_ushort(l0) | ((uint32_t)__bfloat16_as_ushort(l1) << 16);
    return (uint32_t)__bfloat16_as_ushort(h0) | ((uint32_t)__bfloat16_as_ushort(h1) << 16);
}
__device__ __forceinline__ uint32_t pack_h2(float a, float b) {
    __half2 h = __floats2half2_rn(a, b);
    return *(uint32_t*)&h;
}
__device__ __forceinline__ uint32_t pack_h2pair(float v0, float v1, uint32_t& lo) {
    __half h0 = __float2half_rn(v0), h1 = __float2half_rn(v1);
    __half l0 = __float2half_rn(v0 - __half2float(h0));
    __half l1 = __float2half_rn(v1 - __half2float(h1));
    lo = (uint32_t)__half_as_ushort(l0) | ((uint32_t)__half_as_ushort(l1) << 16);
    return (uint32_t)__half_as_ushort(h0) | ((uint32_t)__half_as_ushort(h1) << 16);
}

#define STAGE 65536
#define GSMEM (2 * STAGE)

// ======================= NT GEMM: C[M,N] = (Ahi+Alo)[M,K] @ (Bhi+Blo)[N,K]^T (bf16 3-term) ===========
// MODE 3: single fp16 out; MODE 4: fp16 hi/lo pair out.
template <int MODE>
__global__ __launch_bounds__(512, 1)
void gemm_nt_mma(const bf16* __restrict__ Ahi, const bf16* __restrict__ Alo,
                 const bf16* __restrict__ Bhi, const bf16* __restrict__ Blo,
                 __half* __restrict__ C16, __half* __restrict__ C16lo,
                 int Kdim, long ldA, long ldB, long ldC)
{
    extern __shared__ char sm[];
    const uint32_t sb = smem_u32(sm);
    const int tid = threadIdx.x, wid = tid >> 5, lane = tid & 31;
    const int wm = wid >> 2, wn = wid & 3;
    const long row0 = (long)blockIdx.y * 128, col0 = (long)blockIdx.x * 128;
    const int NC = Kdim / 64;

    uint32_t soff[2]; long aoff[2], boff[2];
#pragma unroll
    for (int j = 0; j < 2; j++) {
        int slot = tid + j * 512;
        int r = slot >> 3, c = slot & 7;
        soff[j] = (uint32_t)(r * 128 + ((c ^ (r & 7)) << 4));
        aoff[j] = (row0 + r) * ldA + c * 8;
        boff[j] = (col0 + r) * ldB + c * 8;
    }

    const int g = lane >> 3, lr = lane & 7;
    const int arow_b = wm * 32 + (g & 1) * 8 + lr;
    const int brow_b = wn * 32 + (g & 1) * 8 + lr;
    const int ch_hi = g >> 1;

    float acc[2][4][4];
#pragma unroll
    for (int i = 0; i < 2; i++)
#pragma unroll
        for (int j = 0; j < 4; j++)
#pragma unroll
            for (int q = 0; q < 4; q++) acc[i][j][q] = 0.0f;

#define NT_LOAD(buf, kb) do {                                                  \
    uint32_t s_ = sb + (uint32_t)(buf) * STAGE;                                \
    _Pragma("unroll")                                                          \
    for (int j = 0; j < 2; j++) {                                              \
        CP16(s_ +         soff[j], Ahi + aoff[j] + (kb));                      \
        CP16(s_ + 16384 + soff[j], Alo + aoff[j] + (kb));                      \
        CP16(s_ + 32768 + soff[j], Bhi + boff[j] + (kb));                      \
        CP16(s_ + 49152 + soff[j], Blo + boff[j] + (kb));                      \
    }                                                                          \
    CP_COMMIT();                                                               \
} while (0)

    NT_LOAD(0, 0);

    for (int i = 0; i < NC; i++) {
        if (i + 1 < NC) { NT_LOAD((i + 1) & 1, (long)(i + 1) * 64); CP_WAIT(1); }
        else            { CP_WAIT(0); }
        __syncthreads();
        const uint32_t As = sb + (uint32_t)(i & 1) * STAGE;
        const uint32_t Bs = As + 32768;

#pragma unroll
        for (int ks = 0; ks < 4; ks++) {
            uint32_t a[2][2][4], b[2][4][2];
#pragma unroll
            for (int comp = 0; comp < 2; comp++) {
#pragma unroll
                for (int mf = 0; mf < 2; mf++) {
                    int row = arow_b + mf * 16;
                    int ch = ks * 2 + ch_hi;
                    ldsm_x4(a[comp][mf], As + comp * 16384u + row * 128 + ((ch ^ (row & 7)) << 4));
                }
#pragma unroll
                for (int np = 0; np < 2; np++) {
                    int row = brow_b + np * 16;
                    int ch = ks * 2 + ch_hi;
                    uint32_t q[4];
                    ldsm_x4(q, Bs + comp * 16384u + row * 128 + ((ch ^ (row & 7)) << 4));
                    b[comp][np * 2][0]     = q[0]; b[comp][np * 2][1]     = q[2];
                    b[comp][np * 2 + 1][0] = q[1]; b[comp][np * 2 + 1][1] = q[3];
                }
            }
#pragma unroll
            for (int mf = 0; mf < 2; mf++)
#pragma unroll
                for (int nf = 0; nf < 4; nf++) {
                    mma16816(acc[mf][nf], a[0][mf], b[0][nf]);
                    mma16816(acc[mf][nf], a[0][mf], b[1][nf]);
                    mma16816(acc[mf][nf], a[1][mf], b[0][nf]);
                }
        }
        __syncthreads();
    }

#pragma unroll
    for (int mf = 0; mf < 2; mf++)
#pragma unroll
        for (int nf = 0; nf < 4; nf++) {
            long row = row0 + wm * 32 + mf * 16 + (lane >> 2);
            long col = col0 + wn * 32 + nf * 8 + (lane & 3) * 2;
            if (MODE == 3) {
                *(uint32_t*)(C16 + row * ldC + col)       = pack_h2(acc[mf][nf][0], acc[mf][nf][1]);
                *(uint32_t*)(C16 + (row + 8) * ldC + col) = pack_h2(acc[mf][nf][2], acc[mf][nf][3]);
            } else {  // MODE 4: fp16 hi/lo pair
                uint32_t lo0, lo1;
                uint32_t h0 = pack_h2pair(acc[mf][nf][0], acc[mf][nf][1], lo0);
                uint32_t h1 = pack_h2pair(acc[mf][nf][2], acc[mf][nf][3], lo1);
                *(uint32_t*)(C16 + row * ldC + col)         = h0;
                *(uint32_t*)(C16lo + row * ldC + col)       = lo0;
                *(uint32_t*)(C16 + (row + 8) * ldC + col)   = h1;
                *(uint32_t*)(C16lo + (row + 8) * ldC + col) = lo1;
            }
        }
#undef NT_LOAD
}

// ======================= S GEMM: C[M,N] = A16[M,K] @ (Bhi+Blo)[N,K]^T (fp16 2-term, 3-stage) =========
#define STAGE_S 49152
#define GSMEM_S (3 * STAGE_S)
__global__ __launch_bounds__(512, 1)
void gemm_s_f16(const __half* __restrict__ A, const __half* __restrict__ Bhi,
                const __half* __restrict__ Blo, float* __restrict__ Cf,
                int Kdim, long ldA, long ldB, long ldC)
{
    extern __shared__ char sm[];
    const uint32_t sb = smem_u32(sm);
    const int tid = threadIdx.x, wid = tid >> 5, lane = tid & 31;
    const int wm = wid >> 2, wn = wid & 3;
    const long row0 = (long)blockIdx.y * 128, col0 = (long)blockIdx.x * 128;
    const int NC = Kdim / 64;

    uint32_t soff[2]; long aoff[2], boff[2];
#pragma unroll
    for (int j = 0; j < 2; j++) {
        int slot = tid + j * 512;
        int r = slot >> 3, c = slot & 7;
        soff[j] = (uint32_t)(r * 128 + ((c ^ (r & 7)) << 4));
        aoff[j] = (row0 + r) * ldA + c * 8;
        boff[j] = (col0 + r) * ldB + c * 8;
    }

    const int g = lane >> 3, lr = lane & 7;
    const int arow_b = wm * 32 + (g & 1) * 8 + lr;
    const int brow_b = wn * 32 + (g & 1) * 8 + lr;
    const int ch_hi = g >> 1;

    float acc[2][4][4];
#pragma unroll
    for (int i = 0; i < 2; i++)
#pragma unroll
        for (int j = 0; j < 4; j++)
#pragma unroll
            for (int q = 0; q < 4; q++) acc[i][j][q] = 0.0f;

#define S_LOAD(buf, kb) do {                                                   \
    uint32_t s_ = sb + (uint32_t)(buf) * STAGE_S;                              \
    _Pragma("unroll")                                                          \
    for (int j = 0; j < 2; j++) {                                              \
        CP16(s_ +         soff[j], A   + aoff[j] + (kb));                      \
        CP16(s_ + 16384 + soff[j], Bhi + boff[j] + (kb));                      \
        CP16(s_ + 32768 + soff[j], Blo + boff[j] + (kb));                      \
    }                                                                          \
    CP_COMMIT();                                                               \
} while (0)

    S_LOAD(0, 0);
    S_LOAD(1, 64);

    for (int i = 0; i < NC; i++) {
        if (i + 2 < NC)      { S_LOAD((i + 2) % 3, (long)(i + 2) * 64); CP_WAIT(2); }
        else if (i + 1 < NC) { CP_WAIT(1); }
        else                 { CP_WAIT(0); }
        __syncthreads();
        const uint32_t As = sb + (uint32_t)(i % 3) * STAGE_S;
        const uint32_t Bs = As + 16384;

#pragma unroll
        for (int ks = 0; ks < 4; ks++) {
            uint32_t a[2][4], b[2][4][2];
#pragma unroll
            for (int mf = 0; mf < 2; mf++) {
                int row = arow_b + mf * 16;
                int ch = ks * 2 + ch_hi;
                ldsm_x4(a[mf], As + row * 128 + ((ch ^ (row & 7)) << 4));
            }
#pragma unroll
            for (int comp = 0; comp < 2; comp++) {
#pragma unroll
                for (int np = 0; np < 2; np++) {
                    int row = brow_b + np * 16;
                    int ch = ks * 2 + ch_hi;
                    uint32_t q[4];
                    ldsm_x4(q, Bs + comp * 16384u + row * 128 + ((ch ^ (row & 7)) << 4));
                    b[comp][np * 2][0]     = q[0]; b[comp][np * 2][1]     = q[2];
                    b[comp][np * 2 + 1][0] = q[1]; b[comp][np * 2 + 1][1] = q[3];
                }
            }
#pragma unroll
            for (int mf = 0; mf < 2; mf++)
#pragma unroll
                for (int nf = 0; nf < 4; nf++) {
                    mma16816h(acc[mf][nf], a[mf], b[0][nf]);
                    mma16816h(acc[mf][nf], a[mf], b[1][nf]);
                }
        }
        __syncthreads();
    }

#pragma unroll
    for (int mf = 0; mf < 2; mf++)
#pragma unroll
        for (int nf = 0; nf < 4; nf++) {
            long row = row0 + wm * 32 + mf * 16 + (lane >> 2);
            long col = col0 + wn * 32 + nf * 8 + (lane & 3) * 2;
            *(float2*)(Cf + row * ldC + col)       = make_float2(acc[mf][nf][0], acc[mf][nf][1]);
            *(float2*)(Cf + (row + 8) * ldC + col) = make_float2(acc[mf][nf][2], acc[mf][nf][3]);
        }
#undef S_LOAD
}

// ======================= NN GEMM (fp16 single-term): C[M,N] = A[M,K] @ B[K,N] =======================
#define STAGE_NN 32768
#define GSMEM_NN (2 * STAGE_NN)
__global__ __launch_bounds__(512, 1)
void gemm_nn_f16(const __half* __restrict__ A, const __half* __restrict__ B,
                 float* __restrict__ Cf, int Kdim, long ldA, long ldB, long ldC)
{
    extern __shared__ char sm[];
    const uint32_t sb = smem_u32(sm);
    const int tid = threadIdx.x, wid = tid >> 5, lane = tid & 31;
    const int wm = wid >> 2, wn = wid & 3;
    const long row0 = (long)blockIdx.y * 128, col0 = (long)blockIdx.x * 128;
    const int NC = Kdim / 64;

    uint32_t soffA[2], soffB[2]; long aoff[2], boff[2];
#pragma unroll
    for (int j = 0; j < 2; j++) {
        int slot = tid + j * 512;
        int ra = slot >> 3, ca = slot & 7;
        soffA[j] = (uint32_t)(ra * 128 + ((ca ^ (ra & 7)) << 4));
        aoff[j]  = (row0 + ra) * ldA + ca * 8;
        int rb = slot >> 4, cb = slot & 15;
        soffB[j] = (uint32_t)(rb * 256 + ((cb ^ (rb & 7)) << 4));
        boff[j]  = (long)rb * ldB + col0 + cb * 8;
    }

    const int g = lane >> 3, lr = lane & 7;
    const int arow_b = wm * 32 + (g & 1) * 8 + lr;
    const int krow_b = (g & 1) * 8 + lr;
    const int bch_b  = wn * 4 + (g >> 1);

    float acc[2][4][4];
#pragma unroll
    for (int i = 0; i < 2; i++)
#pragma unroll
        for (int j = 0; j < 4; j++)
#pragma unroll
            for (int q = 0; q < 4; q++) acc[i][j][q] = 0.0f;

#define NN_LOAD(buf, kb) do {                                                  \
    uint32_t s_ = sb + (uint32_t)(buf) * STAGE_NN;                             \
    long kb_ = (kb);                                                           \
    _Pragma("unroll")                                                          \
    for (int j = 0; j < 2; j++) {                                              \
        CP16(s_ +         soffA[j], A + aoff[j] + kb_);                        \
        CP16(s_ + 16384 + soffB[j], B + boff[j] + kb_ * ldB);                  \
    }                                                                          \
    CP_COMMIT();                                                               \
} while (0)

    NN_LOAD(0, 0);

    for (int i = 0; i < NC; i++) {
        if (i + 1 < NC) { NN_LOAD((i + 1) & 1, (long)(i + 1) * 64); CP_WAIT(1); }
        else            { CP_WAIT(0); }
        __syncthreads();
        const uint32_t As = sb + (uint32_t)(i & 1) * STAGE_NN;
        const uint32_t Bs = As + 16384;

#pragma unroll
        for (int ks = 0; ks < 4; ks++) {
            uint32_t a[2][4], b[4][2];
#pragma unroll
            for (int mf = 0; mf < 2; mf++) {
                int row = arow_b + mf * 16;
                int ch = ks * 2 + (g >> 1);
                ldsm_x4(a[mf], As + row * 128 + ((ch ^ (row & 7)) << 4));
            }
#pragma unroll
            for (int np = 0; np < 2; np++) {
                int krow = krow_b + ks * 16;
                int ch = bch_b + np * 2;
                uint32_t q[4];
                ldsm_x4_t(q, Bs + krow * 256 + ((ch ^ (krow & 7)) << 4));
                b[np * 2][0]     = q[0]; b[np * 2][1]     = q[1];
                b[np * 2 + 1][0] = q[2]; b[np * 2 + 1][1] = q[3];
            }
#pragma unroll
            for (int mf = 0; mf < 2; mf++)
#pragma unroll
                for (int nf = 0; nf < 4; nf++)
                    mma16816h(acc[mf][nf], a[mf], b[nf]);
        }
        __syncthreads();
    }

#pragma unroll
    for (int mf = 0; mf < 2; mf++)
#pragma unroll
        for (int nf = 0; nf < 4; nf++) {
            long row = row0 + wm * 32 + mf * 16 + (lane >> 2);
            long col = col0 + wn * 32 + nf * 8 + (lane & 3) * 2;
            *(float2*)(Cf + row * ldC + col)       = make_float2(acc[mf][nf][0], acc[mf][nf][1]);
            *(float2*)(Cf + (row + 8) * ldC + col) = make_float2(acc[mf][nf][2], acc[mf][nf][3]);
        }
#undef NN_LOAD
}

// ======================= fp32 -> bf16 hi/lo conversion =======================
__global__ __launch_bounds__(256)
void cvt_pair(const float* __restrict__ s, bf16* __restrict__ hi, bf16* __restrict__ lo, long n4)
{
    for (long i = blockIdx.x * 256 + threadIdx.x; i < n4; i += (long)gridDim.x * 256) {
        float4 v = ((const float4*)s)[i];
        uint32_t l0, l1;
        uint32_t h0 = pack_hi(v.x, v.y, l0);
        uint32_t h1 = pack_hi(v.z, v.w, l1);
        ((uint2*)hi)[i] = make_uint2(h0, h1);
        ((uint2*)lo)[i] = make_uint2(l0, l1);
    }
}

// ======================= row softmax S -> P (fp16) =======================
__global__ __launch_bounds__(256)
void softmax_f16(const float* __restrict__ S, __half* __restrict__ P)
{
    const long row = blockIdx.x;
    const float4* rp = (const float4*)(S + row * (long)SEQ);
    const int tid = threadIdx.x;
    const float scale = 0.02209708691207961f;  // 1/sqrt(2048)

    float4 v[8];
    float mx = -INFINITY;
#pragma unroll
    for (int i = 0; i < 8; i++) {
        v[i] = rp[tid + i * 256];
        mx = fmaxf(mx, fmaxf(fmaxf(v[i].x, v[i].y), fmaxf(v[i].z, v[i].w)));
    }

    __shared__ float red[256];
    red[tid] = mx;
    __syncthreads();
    for (int s = 128; s > 0; s >>= 1) {
        if (tid < s) red[tid] = fmaxf(red[tid], red[tid + s]);
        __syncthreads();
    }
    mx = red[0];
    __syncthreads();

    float sum = 0.0f;
#pragma unroll
    for (int i = 0; i < 8; i++) {
        v[i].x = __expf((v[i].x - mx) * scale);
        v[i].y = __expf((v[i].y - mx) * scale);
        v[i].z = __expf((v[i].z - mx) * scale);
        v[i].w = __expf((v[i].w - mx) * scale);
        sum += (v[i].x + v[i].y) + (v[i].z + v[i].w);
    }
    red[tid] = sum;
    __syncthreads();
    for (int s = 128; s > 0; s >>= 1) {
        if (tid < s) red[tid] += red[tid + s];
        __syncthreads();
    }
    const float inv = 1.0f / red[0];

#pragma unroll
    for (int i = 0; i < 8; i++) {
        long idx = row * (long)SEQ + (long)(tid + i * 256) * 4;
        ((uint2*)(P + idx))[0] = make_uint2(pack_h2(v[i].x * inv, v[i].y * inv),
                                            pack_h2(v[i].z * inv, v[i].w * inv));
    }
}

// ======================= launch =======================
extern "C" void kernel_launch(void* const* d_in, const int* in_sizes, int n_in,
                              void* d_out, int out_size)
{
    (void)in_sizes; (void)n_in; (void)out_size;
    const float* X  = (const float*)d_in[0];
    const float* Wq = (const float*)d_in[1];
    const float* Wk = (const float*)d_in[2];
    const float* Wv = (const float*)d_in[3];
    float* O = (float*)d_out;

    bf16 *Xhi, *Xlo, *Wqhi, *Wqlo, *Wkhi, *Wklo, *Wvhi, *Wvlo;
    __half *Q16, *Khi16, *Klo16, *V16, *P16;
    float* Smat;
    cudaGetSymbolAddress((void**)&Xhi, g_Xhi);   cudaGetSymbolAddress((void**)&Xlo, g_Xlo);
    cudaGetSymbolAddress((void**)&Wqhi, g_Wqhi); cudaGetSymbolAddress((void**)&Wqlo, g_Wqlo);
    cudaGetSymbolAddress((void**)&Wkhi, g_Wkhi); cudaGetSymbolAddress((void**)&Wklo, g_Wklo);
    cudaGetSymbolAddress((void**)&Wvhi, g_Wvhi); cudaGetSymbolAddress((void**)&Wvlo, g_Wvlo);
    cudaGetSymbolAddress((void**)&Q16, g_Q16);
    cudaGetSymbolAddress((void**)&Khi16, g_Khi16); cudaGetSymbolAddress((void**)&Klo16, g_Klo16);
    cudaGetSymbolAddress((void**)&V16, g_V16);
    cudaGetSymbolAddress((void**)&P16, g_P16);
    cudaGetSymbolAddress((void**)&Smat, g_S);

    cudaFuncSetAttribute(gemm_nt_mma<3>, cudaFuncAttributeMaxDynamicSharedMemorySize, GSMEM);
    cudaFuncSetAttribute(gemm_nt_mma<4>, cudaFuncAttributeMaxDynamicSharedMemorySize, GSMEM);
    cudaFuncSetAttribute(gemm_s_f16,     cudaFuncAttributeMaxDynamicSharedMemorySize, GSMEM_S);
    cudaFuncSetAttribute(gemm_nn_f16,    cudaFuncAttributeMaxDynamicSharedMemorySize, GSMEM_NN);

    // 1) fp32 -> bf16 hi/lo conversions
    cvt_pair<<<1024, 256>>>(X,  Xhi,  Xlo,  (long)SEQ * DM / 4);
    cvt_pair<<<512,  256>>>(Wq, Wqhi, Wqlo, (long)DM * DM / 4);
    cvt_pair<<<512,  256>>>(Wk, Wkhi, Wklo, (long)DM * DM / 4);
    cvt_pair<<<512,  256>>>(Wv, Wvhi, Wvlo, (long)DM * DM / 4);

    dim3 blk(512);
    // 2) projections (bf16 3-term): Q -> fp16 single, K -> fp16 pair, V -> fp16 single
    dim3 gp(DM / 128, SEQ / 128);
    gemm_nt_mma<3><<<gp, blk, GSMEM>>>(Xhi, Xlo, Wqhi, Wqlo, Q16, nullptr, DM, DM, DM, DM);
    gemm_nt_mma<4><<<gp, blk, GSMEM>>>(Xhi, Xlo, Wkhi, Wklo, Khi16, Klo16, DM, DM, DM, DM);
    gemm_nt_mma<3><<<gp, blk, GSMEM>>>(Xhi, Xlo, Wvhi, Wvlo, V16, nullptr, DM, DM, DM, DM);

    // 3) S = Q16 @ (Khi+Klo)^T  [SEQ,SEQ], K=DM (fp16 2-term, 3-stage)
    dim3 gs(SEQ / 128, SEQ / 128);
    gemm_s_f16<<<gs, blk, GSMEM_S>>>(Q16, Khi16, Klo16, Smat, DM, DM, DM, SEQ);

    // 4) P = softmax(S / sqrt(DM)) -> fp16
    softmax_f16<<<SEQ, 256>>>(Smat, P16);

    // 5) O = P @ V  [SEQ,DM], K=SEQ (fp16 single-term NN)
    dim3 go(DM / 128, SEQ / 128);
    gemm_nn_f16<<<go, blk, GSMEM_NN>>>(P16, V16, O, SEQ, SEQ, DM, DM);
}